// round 11
// baseline (speedup 1.0000x reference)
#include <cuda_runtime.h>
#include <cuda_bf16.h>
#include <cstdint>
#include <math.h>

#define BB 64
#define TT 512
#define EE 256
#define HH 768
#define G4 3072
#define VV 5000

#define NCTA 128          // persistent CTAs, 6 hidden units each
#define UPC  6
#define NKC  48           // K=768 / 16 (bf16 mma k16 chunks)
#define NKH  24           // kc chunks per warp half (split-K)
#define WFRAG_U4_PER_CTA (NKC*3*32)     // 4608 uint4 per CTA (weights, bf16 hi/lo packed)
#define HFRAG_E 49152                   // 64*768 bf16 elements per slot

// ---------------- device scratch ----------------
__device__ float g_proj[(size_t)VV * G4];                 // embed@W_ih^T + biases
__device__ __align__(16) uint4 g_wfrag[(size_t)NCTA * WFRAG_U4_PER_CTA]; // W_hh B-fragments
__device__ float g_hall[(size_t)TT * BB * HH];            // h states [t][b][H] fp32 (FC input)
__device__ __align__(16) __nv_bfloat16 g_fh[2][HFRAG_E];  // h bf16-hi, A-fragment order
__device__ __align__(16) __nv_bfloat16 g_fl[2][HFRAG_E];  // h bf16-lo residual
__device__ unsigned g_cnt = 0;                            // barrier arrive count
__device__ unsigned g_gen = 0;                            // barrier generation

__device__ __forceinline__ float to_tf32(float x){
    uint32_t u; asm("cvt.rna.tf32.f32 %0, %1;" : "=r"(u) : "f"(x));
    return __uint_as_float(u);
}
__device__ __forceinline__ uint32_t fu(float x){ return __float_as_uint(x); }

__device__ __forceinline__ void mma_tf32(float* c, const uint32_t* a, const uint32_t* b){
    asm volatile("mma.sync.aligned.m16n8k8.row.col.f32.tf32.tf32.f32 "
        "{%0,%1,%2,%3}, {%4,%5,%6,%7}, {%8,%9}, {%0,%1,%2,%3};"
        : "+f"(c[0]), "+f"(c[1]), "+f"(c[2]), "+f"(c[3])
        : "r"(a[0]), "r"(a[1]), "r"(a[2]), "r"(a[3]), "r"(b[0]), "r"(b[1]));
}
__device__ __forceinline__ void mma_bf16(float* c, const uint32_t* a, const uint32_t* b){
    asm volatile("mma.sync.aligned.m16n8k16.row.col.f32.bf16.bf16.f32 "
        "{%0,%1,%2,%3}, {%4,%5,%6,%7}, {%8,%9}, {%0,%1,%2,%3};"
        : "+f"(c[0]), "+f"(c[1]), "+f"(c[2]), "+f"(c[3])
        : "r"(a[0]), "r"(a[1]), "r"(a[2]), "r"(a[3]), "r"(b[0]), "r"(b[1]));
}

__device__ __forceinline__ unsigned short bfbits(float x){
    return __bfloat16_as_ushort(__float2bfloat16_rn(x));
}
__device__ __forceinline__ uint32_t pack_bf2(float lo_elem, float hi_elem){
    return (uint32_t)bfbits(lo_elem) | ((uint32_t)bfbits(hi_elem) << 16);
}

// ---------------- prep: fragment-ordered bf16 hi/lo W_hh; zero h slot 1 ----------------
// m16n8k16 B fragment: lane lr=lane>>2 (n), lc=lane&3; b0 = B[k=2lc,2lc+1][n], b1 = B[k=2lc+8,2lc+9][n].
// CTA row n_local in [0,24): u = n_local>>2, gate = n_local&3 -> W_hh row = gate*HH + cta*6 + u.
// uint4 at (cta*NKC + kc)*3*32 + nt*32 + lane = {b0_hi, b1_hi, b0_lo, b1_lo} packed bf16x2.
__global__ void k_prep(const float* __restrict__ Whh){
    int i = blockIdx.x * blockDim.x + threadIdx.x;
    if (i < HFRAG_E){
        g_fh[1][i] = __float2bfloat16(0.f);
        g_fl[1][i] = __float2bfloat16(0.f);
    }
    if (i < NCTA * WFRAG_U4_PER_CTA){
        int cta = i / WFRAG_U4_PER_CTA;
        int j   = i % WFRAG_U4_PER_CTA;
        int kc  = j / 96;
        int j2  = j % 96;
        int nt  = j2 >> 5;
        int lane= j2 & 31;
        int lr = lane >> 2, lc = lane & 3;
        int n_local = nt * 8 + lr;
        int u = n_local >> 2, gate = n_local & 3;
        int grow = gate * HH + cta * UPC + u;
        const float* wr = Whh + (size_t)grow * HH + kc * 16;
        float w00 = wr[2*lc],     w01 = wr[2*lc + 1];
        float w10 = wr[2*lc + 8], w11 = wr[2*lc + 9];
        float h00 = __bfloat162float(__float2bfloat16_rn(w00));
        float h01 = __bfloat162float(__float2bfloat16_rn(w01));
        float h10 = __bfloat162float(__float2bfloat16_rn(w10));
        float h11 = __bfloat162float(__float2bfloat16_rn(w11));
        uint4 v;
        v.x = pack_bf2(h00, h01);
        v.y = pack_bf2(h10, h11);
        v.z = pack_bf2(w00 - h00, w01 - h01);
        v.w = pack_bf2(w10 - h10, w11 - h11);
        g_wfrag[i] = v;
    }
}

// ---------------- generic tf32 GEMM: C = A[M,K] @ B[N,K]^T + bias ----------------
template<bool PERM>
__global__ __launch_bounds__(256) void k_gemm(
    const float* __restrict__ A, const float* __restrict__ Bm, float* __restrict__ C,
    int M, int N, int K, const float* __restrict__ bias1, const float* __restrict__ bias2)
{
    __shared__ float As[128][36];
    __shared__ float Bs[128][36];
    const int tid = threadIdx.x;
    const int w = tid >> 5, lane = tid & 31;
    const int lr = lane >> 2, lc = lane & 3;
    const int m0 = blockIdx.y * 128, n0 = blockIdx.x * 128;
    const int wm = (w >> 1) * 32, wn = (w & 1) * 64;

    float acc[2][8][4];
    #pragma unroll
    for (int i = 0; i < 2; i++)
        #pragma unroll
        for (int j = 0; j < 8; j++)
            #pragma unroll
            for (int q = 0; q < 4; q++) acc[i][j][q] = 0.f;

    float4 pa[4], pb[4];
    #pragma unroll
    for (int i = 0; i < 4; i++){
        int f = tid + i * 256; int r = f >> 3, cf = (f & 7) * 4;
        pa[i] = make_float4(0.f,0.f,0.f,0.f);
        if (m0 + r < M) pa[i] = *(const float4*)(A + (size_t)(m0 + r) * K + cf);
        pb[i] = make_float4(0.f,0.f,0.f,0.f);
        if (n0 + r < N) pb[i] = *(const float4*)(Bm + (size_t)(n0 + r) * K + cf);
    }

    for (int k0 = 0; k0 < K; k0 += 32){
        #pragma unroll
        for (int i = 0; i < 4; i++){
            int f = tid + i * 256; int r = f >> 3, cf = (f & 7) * 4;
            float4 ta = pa[i], tb = pb[i];
            As[r][cf+0] = to_tf32(ta.x); As[r][cf+1] = to_tf32(ta.y);
            As[r][cf+2] = to_tf32(ta.z); As[r][cf+3] = to_tf32(ta.w);
            Bs[r][cf+0] = to_tf32(tb.x); Bs[r][cf+1] = to_tf32(tb.y);
            Bs[r][cf+2] = to_tf32(tb.z); Bs[r][cf+3] = to_tf32(tb.w);
        }
        __syncthreads();
        int k1 = k0 + 32;
        if (k1 < K){
            #pragma unroll
            for (int i = 0; i < 4; i++){
                int f = tid + i * 256; int r = f >> 3, cf = (f & 7) * 4;
                pa[i] = make_float4(0.f,0.f,0.f,0.f);
                if (m0 + r < M) pa[i] = *(const float4*)(A + (size_t)(m0 + r) * K + k1 + cf);
                pb[i] = make_float4(0.f,0.f,0.f,0.f);
                if (n0 + r < N) pb[i] = *(const float4*)(Bm + (size_t)(n0 + r) * K + k1 + cf);
            }
        }
        #pragma unroll
        for (int kk = 0; kk < 32; kk += 8){
            uint32_t af[2][4], bf[8][2];
            #pragma unroll
            for (int mt = 0; mt < 2; mt++){
                int rb = wm + mt * 16;
                af[mt][0] = fu(As[rb + lr][kk + lc]);
                af[mt][1] = fu(As[rb + 8 + lr][kk + lc]);
                af[mt][2] = fu(As[rb + lr][kk + lc + 4]);
                af[mt][3] = fu(As[rb + 8 + lr][kk + lc + 4]);
            }
            #pragma unroll
            for (int nt = 0; nt < 8; nt++){
                int cb = wn + nt * 8;
                bf[nt][0] = fu(Bs[cb + lr][kk + lc]);
                bf[nt][1] = fu(Bs[cb + lr][kk + lc + 4]);
            }
            #pragma unroll
            for (int mt = 0; mt < 2; mt++)
                #pragma unroll
                for (int nt = 0; nt < 8; nt++)
                    mma_tf32(acc[mt][nt], af[mt], bf[nt]);
        }
        __syncthreads();
    }

    #pragma unroll
    for (int mt = 0; mt < 2; mt++)
        #pragma unroll
        for (int nt = 0; nt < 8; nt++){
            #pragma unroll
            for (int q = 0; q < 4; q++){
                int row = m0 + wm + mt * 16 + lr + (q >> 1) * 8;
                int col = n0 + wn + nt * 8 + lc * 2 + (q & 1);
                if (row < M && col < N){
                    float v = acc[mt][nt][q];
                    if (bias1) v += bias1[col];
                    if (bias2) v += bias2[col];
                    int orow = row;
                    if (PERM){ int t = row >> 6, b = row & 63; orow = b * TT + t; }
                    C[(size_t)orow * N + col] = v;
                }
            }
        }
}

// ---------------- persistent LSTM recurrence (bf16x3, split-K, 8 warps) ----------------
// 128 CTAs x 256 threads. Warp w: wk = w>>2 selects K half, wm = w&3 selects batch m16 tile.
// Each warp: m16 x n24 (3 n8 tiles) over 24 kc chunks. Partial gates -> 2 smem buffers -> epilogue sum.
__global__ __launch_bounds__(256, 1) void k_persist(const int* __restrict__ x)
{
    extern __shared__ float sm[];
    uint4* Bsm = (uint4*)sm;                        // 4608 uint4 = 73728 B
    float* gs0 = sm + WFRAG_U4_PER_CTA * 4;         // 64 x 25 floats (K-half 0)
    float* gs1 = gs0 + 64 * 25;                     // 64 x 25 floats (K-half 1)
    const int tid  = threadIdx.x;
    const int w    = tid >> 5, lane = tid & 31;
    const int wk   = w >> 2, wm = w & 3;
    const int lr   = lane >> 2, lc2 = (lane & 3) * 2;
    const int cta  = blockIdx.x;
    float* gw = wk ? gs1 : gs0;

    // persistent weight slice -> smem
    {
        const uint4* wsrc = g_wfrag + (size_t)cta * WFRAG_U4_PER_CTA;
        for (int i = tid; i < WFRAG_U4_PER_CTA; i += 256) Bsm[i] = wsrc[i];
    }

    // epilogue work items: up to 2 per thread -> (b, u); 384 items total
    int eb[2], eu[2]; float creg[2]; const int* xp[2]; bool ev[2];
    #pragma unroll
    for (int j = 0; j < 2; j++){
        int idx = tid + j * 256;
        ev[j] = (idx < 384);
        eb[j] = idx & 63; eu[j] = (idx >> 6) & 7;
        creg[j] = 0.f;
        xp[j] = x + eb[j] * TT;
    }
    __syncthreads();

    unsigned genbase = 0;
    if (tid == 0)
        asm volatile("ld.volatile.global.u32 %0, [%1];" : "=r"(genbase) : "l"(&g_gen));

    for (int t = 0; t < TT; t++){
        // prefetch proj gate biases (consumed in epilogue; hidden behind GEMM)
        float pv[2][4];
        #pragma unroll
        for (int j = 0; j < 2; j++){
            if (ev[j]){
                int xv = __ldg(xp[j] + t);
                const float* pr = g_proj + (size_t)xv * G4 + (cta * UPC + eu[j]);
                #pragma unroll
                for (int g = 0; g < 4; g++) pv[j][g] = __ldg(pr + g * HH);
            }
        }

        const uint4* Ahi = (const uint4*)g_fh[(t + 1) & 1];  // slot (t-1)&1; t=0 -> zeroed slot 1
        const uint4* Alo = (const uint4*)g_fl[(t + 1) & 1];

        float accHH[3][4], accHL[3][4], accLH[3][4];
        #pragma unroll
        for (int n = 0; n < 3; n++)
            #pragma unroll
            for (int q = 0; q < 4; q++){ accHH[n][q] = 0.f; accHL[n][q] = 0.f; accLH[n][q] = 0.f; }

        // 6-deep A-fragment prefetch ring over this warp's 24 kc chunks
        uint4 ahb[6], alb[6];
        #pragma unroll
        for (int j = 0; j < 6; j++){
            int kc = wk * NKH + j;
            int off = (kc * 4 + wm) * 32 + lane;
            ahb[j] = __ldg(Ahi + off);
            alb[j] = __ldg(Alo + off);
        }
        uint4 bcur[3], bnxt[3];
        #pragma unroll
        for (int nt = 0; nt < 3; nt++)
            bcur[nt] = Bsm[((wk * NKH) * 3 + nt) * 32 + lane];

        for (int c = 0; c < 4; c++){
            #pragma unroll
            for (int j = 0; j < 6; j++){
                int kl = c * 6 + j;                 // 0..23 within half
                int kc = wk * NKH + kl;
                uint4 a4 = ahb[j], l4 = alb[j];
                int knl = kl + 6;
                if (knl < NKH){
                    int kn = wk * NKH + knl;
                    int off = (kn * 4 + wm) * 32 + lane;
                    ahb[j] = __ldg(Ahi + off);
                    alb[j] = __ldg(Alo + off);
                }
                if (kl + 1 < NKH){
                    #pragma unroll
                    for (int nt = 0; nt < 3; nt++)
                        bnxt[nt] = Bsm[((kc + 1) * 3 + nt) * 32 + lane];
                }
                uint32_t ah[4] = {a4.x, a4.y, a4.z, a4.w};
                uint32_t al[4] = {l4.x, l4.y, l4.z, l4.w};
                #pragma unroll
                for (int nt = 0; nt < 3; nt++){
                    uint32_t bh[2] = {bcur[nt].x, bcur[nt].y};
                    uint32_t bl[2] = {bcur[nt].z, bcur[nt].w};
                    mma_bf16(accHH[nt], ah, bh);
                    mma_bf16(accHL[nt], ah, bl);
                    mma_bf16(accLH[nt], al, bh);
                }
                #pragma unroll
                for (int nt = 0; nt < 3; nt++) bcur[nt] = bnxt[nt];
            }
        }

        // partial gate tile -> this K-half's smem buffer
        #pragma unroll
        for (int nt = 0; nt < 3; nt++){
            #pragma unroll
            for (int q = 0; q < 4; q++){
                int row = wm * 16 + lr + (q >> 1) * 8;
                int col = nt * 8 + lc2 + (q & 1);
                gw[row * 25 + col] = accHH[nt][q] + accHL[nt][q] + accLH[nt][q];
            }
        }
        __syncthreads();

        // pointwise LSTM + h scatter
        __nv_bfloat16* hdst_hi = g_fh[t & 1];
        __nv_bfloat16* hdst_lo = g_fl[t & 1];
        float* hall_t = g_hall + (size_t)t * (BB * HH);
        #pragma unroll
        for (int j = 0; j < 2; j++){
            if (!ev[j]) continue;
            int b = eb[j], u = eu[j], ug = cta * UPC + u;
            float gi = gs0[b * 25 + 4*u + 0] + gs1[b * 25 + 4*u + 0] + pv[j][0];
            float gf = gs0[b * 25 + 4*u + 1] + gs1[b * 25 + 4*u + 1] + pv[j][1];
            float gg = gs0[b * 25 + 4*u + 2] + gs1[b * 25 + 4*u + 2] + pv[j][2];
            float go = gs0[b * 25 + 4*u + 3] + gs1[b * 25 + 4*u + 3] + pv[j][3];
            float si = 1.f / (1.f + expf(-gi));
            float sf = 1.f / (1.f + expf(-gf));
            float so = 1.f / (1.f + expf(-go));
            float cnew = sf * creg[j] + si * tanhf(gg);
            float hnew = so * tanhf(cnew);
            creg[j] = cnew;
            hall_t[b * HH + ug] = hnew;
            // A-fragment scatter: kc = ug>>4, kk = ug&15; r = b&15, wb = b>>4
            int kc = ug >> 4, kk = ug & 15;
            int r = b & 15, wb = b >> 4;
            int lane_h = (r & 7) * 4 + ((kk & 7) >> 1);
            int reg = (r >> 3) + 2 * (kk >> 3);
            int half = kk & 1;
            int elem = (((kc * 4 + wb) * 32 + lane_h) * 4 + reg) * 2 + half;
            __nv_bfloat16 hb = __float2bfloat16_rn(hnew);
            hdst_hi[elem] = hb;
            hdst_lo[elem] = __float2bfloat16_rn(hnew - __bfloat162float(hb));
        }

        // grid barrier (generation-based, self-resetting)
        __threadfence();
        __syncthreads();
        if (tid == 0){
            genbase += 1;
            unsigned arrived = atomicAdd(&g_cnt, 1u);
            if (arrived == NCTA - 1){
                asm volatile("st.volatile.global.u32 [%0], %1;" :: "l"(&g_cnt), "r"(0u));
                __threadfence();
                atomicAdd(&g_gen, 1u);
            } else {
                unsigned cur;
                do {
                    asm volatile("ld.acquire.gpu.global.u32 %0, [%1];" : "=r"(cur) : "l"(&g_gen));
                } while ((int)(cur - genbase) < 0);
            }
        }
        __syncthreads();
    }
}

// ---------------- host launch ----------------
extern "C" void kernel_launch(void* const* d_in, const int* in_sizes, int n_in,
                              void* d_out, int out_size)
{
    const int* x = 0;
    const float *embed = 0, *W_ih = 0, *W_hh = 0, *b_ih = 0, *b_hh = 0, *fc_w = 0, *fc_b = 0;
    for (int i = 0; i < n_in; i++){
        switch (in_sizes[i]){
            case BB*TT:      x     = (const int*)  d_in[i]; break;
            case VV*EE:      embed = (const float*)d_in[i]; break;
            case G4*EE:      W_ih  = (const float*)d_in[i]; break;
            case G4*HH:      W_hh  = (const float*)d_in[i]; break;
            case G4:         if (!b_ih) b_ih = (const float*)d_in[i];
                             else        b_hh = (const float*)d_in[i]; break;
            case VV*HH:      fc_w  = (const float*)d_in[i]; break;
            case VV:         fc_b  = (const float*)d_in[i]; break;
            default: break;  // truncate_length — identity in forward pass
        }
    }
    float* out = (float*)d_out;

    float *p_proj = 0, *p_hall = 0;
    cudaGetSymbolAddress((void**)&p_proj, g_proj);
    cudaGetSymbolAddress((void**)&p_hall, g_hall);

    const int SMEM = WFRAG_U4_PER_CTA * 16 + 2 * 64 * 25 * 4;   // 73728 + 12800 = 86528
    cudaFuncSetAttribute(k_persist, cudaFuncAttributeMaxDynamicSharedMemorySize, SMEM);

    // 1) prep: fragment-ordered bf16 W_hh hi/lo + zero h slot 1 (replay-safe)
    {
        int n = NCTA * WFRAG_U4_PER_CTA;   // 589,824
        k_prep<<<(n + 255) / 256, 256>>>(W_hh);
    }
    // 2) proj[V,4H] = embed @ W_ih^T + b_ih + b_hh
    {
        dim3 grid(G4 / 128, (VV + 127) / 128);
        k_gemm<false><<<grid, 256>>>(embed, W_ih, p_proj, VV, G4, EE, b_ih, b_hh);
    }
    // 3) persistent recurrence: 512 steps, 1 launch
    k_persist<<<NCTA, 256, SMEM>>>(x);
    // 4) out[B,T,V] = hall @ fc_w^T + fc_b
    {
        dim3 grid((VV + 127) / 128, (BB * TT) / 128);
        k_gemm<true><<<grid, 256>>>(p_hall, fc_w, out, BB * TT, VV, HH, fc_b, (const float*)0);
    }
}

// round 13
// speedup vs baseline: 1.0524x; 1.0524x over previous
#include <cuda_runtime.h>
#include <cuda_fp16.h>
#include <cstdint>
#include <math.h>

#define BB 64
#define TT 512
#define EE 256
#define HH 768
#define G4 3072
#define VV 5000

#define NCTA 128          // persistent CTAs, 6 hidden units each
#define UPC  6
#define NKC  48           // K=768 / 16 (fp16 mma k16 chunks)
#define WFRAG_U4_PER_CTA (NKC*3*32)     // 4608 uint4 per CTA (W_hh fp16 hi/lo packed)
#define HFRAG_E 49152                   // 64*768 fp16 elements per slot

// ---------------- device scratch ----------------
__device__ float g_proj[(size_t)VV * G4];                 // embed@W_ih^T + biases
__device__ __align__(16) uint4 g_wfrag[(size_t)NCTA * WFRAG_U4_PER_CTA]; // W_hh B-fragments
__device__ float g_hall[(size_t)TT * BB * HH];            // h states [t][b][H] fp32 (FC input)
__device__ __align__(16) __half g_fh[2][HFRAG_E];         // h fp16, A-fragment order, double-buffered
__device__ unsigned g_cnt = 0;                            // barrier arrive count
__device__ unsigned g_gen = 0;                            // barrier generation

__device__ __forceinline__ float to_tf32(float x){
    uint32_t u; asm("cvt.rna.tf32.f32 %0, %1;" : "=r"(u) : "f"(x));
    return __uint_as_float(u);
}
__device__ __forceinline__ uint32_t fu(float x){ return __float_as_uint(x); }

__device__ __forceinline__ void mma_tf32(float* c, const uint32_t* a, const uint32_t* b){
    asm volatile("mma.sync.aligned.m16n8k8.row.col.f32.tf32.tf32.f32 "
        "{%0,%1,%2,%3}, {%4,%5,%6,%7}, {%8,%9}, {%0,%1,%2,%3};"
        : "+f"(c[0]), "+f"(c[1]), "+f"(c[2]), "+f"(c[3])
        : "r"(a[0]), "r"(a[1]), "r"(a[2]), "r"(a[3]), "r"(b[0]), "r"(b[1]));
}
__device__ __forceinline__ void mma_fp16(float* c, const uint32_t* a, const uint32_t* b){
    asm volatile("mma.sync.aligned.m16n8k16.row.col.f32.f16.f16.f32 "
        "{%0,%1,%2,%3}, {%4,%5,%6,%7}, {%8,%9}, {%0,%1,%2,%3};"
        : "+f"(c[0]), "+f"(c[1]), "+f"(c[2]), "+f"(c[3])
        : "r"(a[0]), "r"(a[1]), "r"(a[2]), "r"(a[3]), "r"(b[0]), "r"(b[1]));
}

__device__ __forceinline__ uint32_t pack_h2(float lo_elem, float hi_elem){
    // lower k element in lower 16 bits
    return (uint32_t)__half_as_ushort(__float2half_rn(lo_elem))
         | ((uint32_t)__half_as_ushort(__float2half_rn(hi_elem)) << 16);
}

// ---------------- prep: fragment-ordered fp16 hi/lo W_hh; zero h slot 1 ----------------
// m16n8k16 B fragment: lane lr=lane>>2 (n), lc=lane&3; b0 = B[k=2lc,2lc+1][n], b1 = B[k=2lc+8,2lc+9][n].
// CTA row n_local in [0,24): u = n_local>>2, gate = n_local&3 -> W_hh row = gate*HH + cta*6 + u.
// uint4 at (cta*NKC + kc)*3*32 + nt*32 + lane = {b0_hi, b1_hi, b0_lo, b1_lo} packed fp16x2.
__global__ void k_prep(const float* __restrict__ Whh){
    int i = blockIdx.x * blockDim.x + threadIdx.x;
    if (i < HFRAG_E) g_fh[1][i] = __float2half(0.f);
    if (i < NCTA * WFRAG_U4_PER_CTA){
        int cta = i / WFRAG_U4_PER_CTA;
        int j   = i % WFRAG_U4_PER_CTA;
        int kc  = j / 96;
        int j2  = j % 96;
        int nt  = j2 >> 5;
        int lane= j2 & 31;
        int lr = lane >> 2, lc = lane & 3;
        int n_local = nt * 8 + lr;
        int u = n_local >> 2, gate = n_local & 3;
        int grow = gate * HH + cta * UPC + u;
        const float* wr = Whh + (size_t)grow * HH + kc * 16;
        float w00 = wr[2*lc],     w01 = wr[2*lc + 1];
        float w10 = wr[2*lc + 8], w11 = wr[2*lc + 9];
        float h00 = __half2float(__float2half_rn(w00));
        float h01 = __half2float(__float2half_rn(w01));
        float h10 = __half2float(__float2half_rn(w10));
        float h11 = __half2float(__float2half_rn(w11));
        uint4 v;
        v.x = pack_h2(h00, h01);
        v.y = pack_h2(h10, h11);
        v.z = pack_h2(w00 - h00, w01 - h01);
        v.w = pack_h2(w10 - h10, w11 - h11);
        g_wfrag[i] = v;
    }
}

// ---------------- generic tf32 GEMM: C = A[M,K] @ B[N,K]^T + bias ----------------
template<bool PERM>
__global__ __launch_bounds__(256) void k_gemm(
    const float* __restrict__ A, const float* __restrict__ Bm, float* __restrict__ C,
    int M, int N, int K, const float* __restrict__ bias1, const float* __restrict__ bias2)
{
    __shared__ float As[128][36];
    __shared__ float Bs[128][36];
    const int tid = threadIdx.x;
    const int w = tid >> 5, lane = tid & 31;
    const int lr = lane >> 2, lc = lane & 3;
    const int m0 = blockIdx.y * 128, n0 = blockIdx.x * 128;
    const int wm = (w >> 1) * 32, wn = (w & 1) * 64;

    float acc[2][8][4];
    #pragma unroll
    for (int i = 0; i < 2; i++)
        #pragma unroll
        for (int j = 0; j < 8; j++)
            #pragma unroll
            for (int q = 0; q < 4; q++) acc[i][j][q] = 0.f;

    float4 pa[4], pb[4];
    #pragma unroll
    for (int i = 0; i < 4; i++){
        int f = tid + i * 256; int r = f >> 3, cf = (f & 7) * 4;
        pa[i] = make_float4(0.f,0.f,0.f,0.f);
        if (m0 + r < M) pa[i] = *(const float4*)(A + (size_t)(m0 + r) * K + cf);
        pb[i] = make_float4(0.f,0.f,0.f,0.f);
        if (n0 + r < N) pb[i] = *(const float4*)(Bm + (size_t)(n0 + r) * K + cf);
    }

    for (int k0 = 0; k0 < K; k0 += 32){
        #pragma unroll
        for (int i = 0; i < 4; i++){
            int f = tid + i * 256; int r = f >> 3, cf = (f & 7) * 4;
            float4 ta = pa[i], tb = pb[i];
            As[r][cf+0] = to_tf32(ta.x); As[r][cf+1] = to_tf32(ta.y);
            As[r][cf+2] = to_tf32(ta.z); As[r][cf+3] = to_tf32(ta.w);
            Bs[r][cf+0] = to_tf32(tb.x); Bs[r][cf+1] = to_tf32(tb.y);
            Bs[r][cf+2] = to_tf32(tb.z); Bs[r][cf+3] = to_tf32(tb.w);
        }
        __syncthreads();
        int k1 = k0 + 32;
        if (k1 < K){
            #pragma unroll
            for (int i = 0; i < 4; i++){
                int f = tid + i * 256; int r = f >> 3, cf = (f & 7) * 4;
                pa[i] = make_float4(0.f,0.f,0.f,0.f);
                if (m0 + r < M) pa[i] = *(const float4*)(A + (size_t)(m0 + r) * K + k1 + cf);
                pb[i] = make_float4(0.f,0.f,0.f,0.f);
                if (n0 + r < N) pb[i] = *(const float4*)(Bm + (size_t)(n0 + r) * K + k1 + cf);
            }
        }
        #pragma unroll
        for (int kk = 0; kk < 32; kk += 8){
            uint32_t af[2][4], bf[8][2];
            #pragma unroll
            for (int mt = 0; mt < 2; mt++){
                int rb = wm + mt * 16;
                af[mt][0] = fu(As[rb + lr][kk + lc]);
                af[mt][1] = fu(As[rb + 8 + lr][kk + lc]);
                af[mt][2] = fu(As[rb + lr][kk + lc + 4]);
                af[mt][3] = fu(As[rb + 8 + lr][kk + lc + 4]);
            }
            #pragma unroll
            for (int nt = 0; nt < 8; nt++){
                int cb = wn + nt * 8;
                bf[nt][0] = fu(Bs[cb + lr][kk + lc]);
                bf[nt][1] = fu(Bs[cb + lr][kk + lc + 4]);
            }
            #pragma unroll
            for (int mt = 0; mt < 2; mt++)
                #pragma unroll
                for (int nt = 0; nt < 8; nt++)
                    mma_tf32(acc[mt][nt], af[mt], bf[nt]);
        }
        __syncthreads();
    }

    #pragma unroll
    for (int mt = 0; mt < 2; mt++)
        #pragma unroll
        for (int nt = 0; nt < 8; nt++){
            #pragma unroll
            for (int q = 0; q < 4; q++){
                int row = m0 + wm + mt * 16 + lr + (q >> 1) * 8;
                int col = n0 + wn + nt * 8 + lc * 2 + (q & 1);
                if (row < M && col < N){
                    float v = acc[mt][nt][q];
                    if (bias1) v += bias1[col];
                    if (bias2) v += bias2[col];
                    int orow = row;
                    if (PERM){ int t = row >> 6, b = row & 63; orow = b * TT + t; }
                    C[(size_t)orow * N + col] = v;
                }
            }
        }
}

// ---------------- persistent LSTM recurrence (fp16 2-product) ----------------
// 128 CTAs x 128 threads. Warp w: batch rows [w*16, w*16+16), all 24 gate cols (3 n8 tiles).
// gates = A(h fp16) x (B_hi + B_lo), fp32 accumulate. W fp16 hi/lo => W error ~2^-24.
__global__ __launch_bounds__(128, 1) void k_persist(const int* __restrict__ x)
{
    extern __shared__ float sm[];
    uint4* Bsm = (uint4*)sm;                 // 4608 uint4 = 73728 B
    float*  gs = sm + 4*WFRAG_U4_PER_CTA;    // 64 x 25 floats
    const int tid  = threadIdx.x;
    const int w    = tid >> 5, lane = tid & 31;
    const int lr   = lane >> 2, lc2 = (lane & 3) * 2;
    const int cta  = blockIdx.x;

    // persistent weight slice -> smem (fragment order, straight copy)
    {
        const uint4* wsrc = g_wfrag + (size_t)cta * WFRAG_U4_PER_CTA;
        for (int i = tid; i < WFRAG_U4_PER_CTA; i += 128) Bsm[i] = wsrc[i];
    }

    // epilogue work items: 3 per thread -> (b, u); 384 items
    int eb[3], eu[3]; float creg[3];
    const int* xp[3];
    #pragma unroll
    for (int j = 0; j < 3; j++){
        int idx = tid + j * 128;
        eb[j] = idx & 63; eu[j] = idx >> 6;
        creg[j] = 0.f;
        xp[j] = x + eb[j] * TT;
    }
    __syncthreads();

    unsigned genbase = 0;
    if (tid == 0)
        asm volatile("ld.volatile.global.u32 %0, [%1];" : "=r"(genbase) : "l"(&g_gen));

    for (int t = 0; t < TT; t++){
        // prefetch proj gate biases (consumed in epilogue; hidden behind GEMM)
        float pv[3][4];
        #pragma unroll
        for (int j = 0; j < 3; j++){
            int xv = __ldg(xp[j] + t);
            const float* pr = g_proj + (size_t)xv * G4 + (cta * UPC + eu[j]);
            #pragma unroll
            for (int g = 0; g < 4; g++) pv[j][g] = __ldg(pr + g * HH);
        }

        const uint4* Ah = (const uint4*)g_fh[(t + 1) & 1];   // slot (t-1)&1; t=0 -> zeroed slot 1

        float accH[3][4], accL[3][4];
        #pragma unroll
        for (int n = 0; n < 3; n++)
            #pragma unroll
            for (int q = 0; q < 4; q++){ accH[n][q] = 0.f; accL[n][q] = 0.f; }

        // 8-deep A-fragment prefetch ring over 48 kc chunks
        uint4 ahb[8];
        #pragma unroll
        for (int j = 0; j < 8; j++)
            ahb[j] = __ldg(Ah + (j * 4 + w) * 32 + lane);
        uint4 bcur[3], bnxt[3];
        #pragma unroll
        for (int nt = 0; nt < 3; nt++) bcur[nt] = Bsm[nt * 32 + lane];

        for (int c = 0; c < 6; c++){
            #pragma unroll
            for (int j = 0; j < 8; j++){
                int kc = c * 8 + j;
                uint4 a4 = ahb[j];
                int kn = kc + 8;
                if (kn < NKC)
                    ahb[j] = __ldg(Ah + (kn * 4 + w) * 32 + lane);
                if (kc + 1 < NKC){
                    #pragma unroll
                    for (int nt = 0; nt < 3; nt++)
                        bnxt[nt] = Bsm[((kc + 1) * 3 + nt) * 32 + lane];
                }
                uint32_t ah[4] = {a4.x, a4.y, a4.z, a4.w};
                #pragma unroll
                for (int nt = 0; nt < 3; nt++){
                    uint32_t bh[2] = {bcur[nt].x, bcur[nt].y};
                    uint32_t bl[2] = {bcur[nt].z, bcur[nt].w};
                    mma_fp16(accH[nt], ah, bh);
                    mma_fp16(accL[nt], ah, bl);
                }
                #pragma unroll
                for (int nt = 0; nt < 3; nt++) bcur[nt] = bnxt[nt];
            }
        }

        // gate tile -> smem (C fragment: row = w*16 + lr + (q>>1)*8, col = nt*8 + lc2 + (q&1))
        #pragma unroll
        for (int nt = 0; nt < 3; nt++){
            #pragma unroll
            for (int q = 0; q < 4; q++){
                int row = w * 16 + lr + (q >> 1) * 8;
                int col = nt * 8 + lc2 + (q & 1);
                gs[row * 25 + col] = accH[nt][q] + accL[nt][q];
            }
        }
        __syncthreads();

        // pointwise LSTM + h scatter (row-major fp32 for FC, A-fragment fp16 for next step)
        __half* hdst = g_fh[t & 1];
        float* hall_t = g_hall + (size_t)t * (BB * HH);
        #pragma unroll
        for (int j = 0; j < 3; j++){
            int b = eb[j], u = eu[j], ug = cta * UPC + u;
            float gi = gs[b * 25 + 4*u + 0] + pv[j][0];
            float gf = gs[b * 25 + 4*u + 1] + pv[j][1];
            float gg = gs[b * 25 + 4*u + 2] + pv[j][2];
            float go = gs[b * 25 + 4*u + 3] + pv[j][3];
            float si = 1.f / (1.f + expf(-gi));
            float sf = 1.f / (1.f + expf(-gf));
            float so = 1.f / (1.f + expf(-go));
            float cnew = sf * creg[j] + si * tanhf(gg);
            float hnew = so * tanhf(cnew);
            creg[j] = cnew;
            hall_t[b * HH + ug] = hnew;
            // A-fragment scatter (verified in R9): kc = ug>>4, kk = ug&15; r = b&15, wb = b>>4
            int kc = ug >> 4, kk = ug & 15;
            int r = b & 15, wb = b >> 4;
            int lane_h = (r & 7) * 4 + ((kk & 7) >> 1);
            int reg = (r >> 3) + 2 * (kk >> 3);
            int half = kk & 1;
            int elem = (((kc * 4 + wb) * 32 + lane_h) * 4 + reg) * 2 + half;
            hdst[elem] = __float2half_rn(hnew);
        }

        // grid barrier (generation-based, self-resetting)
        __threadfence();
        __syncthreads();
        if (tid == 0){
            genbase += 1;
            unsigned arrived = atomicAdd(&g_cnt, 1u);
            if (arrived == NCTA - 1){
                asm volatile("st.volatile.global.u32 [%0], %1;" :: "l"(&g_cnt), "r"(0u));
                __threadfence();
                atomicAdd(&g_gen, 1u);
            } else {
                unsigned cur;
                do {
                    asm volatile("ld.acquire.gpu.global.u32 %0, [%1];" : "=r"(cur) : "l"(&g_gen));
                } while ((int)(cur - genbase) < 0);
            }
        }
        __syncthreads();
    }
}

// ---------------- host launch ----------------
extern "C" void kernel_launch(void* const* d_in, const int* in_sizes, int n_in,
                              void* d_out, int out_size)
{
    const int* x = 0;
    const float *embed = 0, *W_ih = 0, *W_hh = 0, *b_ih = 0, *b_hh = 0, *fc_w = 0, *fc_b = 0;
    for (int i = 0; i < n_in; i++){
        switch (in_sizes[i]){
            case BB*TT:      x     = (const int*)  d_in[i]; break;
            case VV*EE:      embed = (const float*)d_in[i]; break;
            case G4*EE:      W_ih  = (const float*)d_in[i]; break;
            case G4*HH:      W_hh  = (const float*)d_in[i]; break;
            case G4:         if (!b_ih) b_ih = (const float*)d_in[i];
                             else        b_hh = (const float*)d_in[i]; break;
            case VV*HH:      fc_w  = (const float*)d_in[i]; break;
            case VV:         fc_b  = (const float*)d_in[i]; break;
            default: break;  // truncate_length — identity in forward pass
        }
    }
    float* out = (float*)d_out;

    float *p_proj = 0, *p_hall = 0;
    cudaGetSymbolAddress((void**)&p_proj, g_proj);
    cudaGetSymbolAddress((void**)&p_hall, g_hall);

    const int SMEM = WFRAG_U4_PER_CTA * 16 + 64 * 25 * 4;   // 73728 + 6400 = 80128
    cudaFuncSetAttribute(k_persist, cudaFuncAttributeMaxDynamicSharedMemorySize, SMEM);

    // 1) prep: fragment-ordered fp16 W_hh hi/lo + zero h slot 1 (replay-safe)
    {
        int n = NCTA * WFRAG_U4_PER_CTA;   // 589,824
        k_prep<<<(n + 255) / 256, 256>>>(W_hh);
    }
    // 2) proj[V,4H] = embed @ W_ih^T + b_ih + b_hh
    {
        dim3 grid(G4 / 128, (VV + 127) / 128);
        k_gemm<false><<<grid, 256>>>(embed, W_ih, p_proj, VV, G4, EE, b_ih, b_hh);
    }
    // 3) persistent recurrence: 512 steps, 1 launch
    k_persist<<<NCTA, 128, SMEM>>>(x);
    // 4) out[B,T,V] = hall @ fc_w^T + fc_b
    {
        dim3 grid((VV + 127) / 128, (BB * TT) / 128);
        k_gemm<true><<<grid, 256>>>(p_hall, fc_w, out, BB * TT, VV, HH, fc_b, (const float*)0);
    }
}

// round 14
// speedup vs baseline: 1.0758x; 1.0222x over previous
#include <cuda_runtime.h>
#include <cuda_fp16.h>
#include <cstdint>
#include <math.h>

#define BB 64
#define TT 512
#define EE 256
#define HH 768
#define G4 3072
#define VV 5000

#define NCTA 128          // persistent CTAs, 6 hidden units each
#define UPC  6
#define NKC  48           // K=768 / 16 (fp16 mma k16 chunks)
#define WFRAG_U4_PER_CTA (NKC*3*32)     // 4608 uint4 per CTA (W_hh fp16 hi/lo packed)
#define HFRAG_E 49152                   // 64*768 fp16 elements per slot

// ---------------- device scratch ----------------
__device__ float g_proj[(size_t)VV * G4];                 // embed@W_ih^T + biases
__device__ __align__(16) uint4 g_wfrag[(size_t)NCTA * WFRAG_U4_PER_CTA]; // W_hh B-fragments
__device__ __align__(16) __half g_hallh[(size_t)TT * BB * HH]; // h states [t][b][H] fp16 (FC input)
__device__ __align__(16) __half g_fh[2][HFRAG_E];         // h fp16, A-fragment order, double-buffered
__device__ __align__(16) __half g_fcwh[(size_t)VV * HH];  // fc_w fp16
__device__ unsigned g_flag[NCTA * 32];                    // arrival flags, 128B-spaced
__device__ unsigned g_gen = 0;                            // release generation (monotonic)

__device__ __forceinline__ float to_tf32(float x){
    uint32_t u; asm("cvt.rna.tf32.f32 %0, %1;" : "=r"(u) : "f"(x));
    return __uint_as_float(u);
}
__device__ __forceinline__ uint32_t fu(float x){ return __float_as_uint(x); }

__device__ __forceinline__ void mma_tf32(float* c, const uint32_t* a, const uint32_t* b){
    asm volatile("mma.sync.aligned.m16n8k8.row.col.f32.tf32.tf32.f32 "
        "{%0,%1,%2,%3}, {%4,%5,%6,%7}, {%8,%9}, {%0,%1,%2,%3};"
        : "+f"(c[0]), "+f"(c[1]), "+f"(c[2]), "+f"(c[3])
        : "r"(a[0]), "r"(a[1]), "r"(a[2]), "r"(a[3]), "r"(b[0]), "r"(b[1]));
}
__device__ __forceinline__ void mma_fp16(float* c, const uint32_t* a, const uint32_t* b){
    asm volatile("mma.sync.aligned.m16n8k16.row.col.f32.f16.f16.f32 "
        "{%0,%1,%2,%3}, {%4,%5,%6,%7}, {%8,%9}, {%0,%1,%2,%3};"
        : "+f"(c[0]), "+f"(c[1]), "+f"(c[2]), "+f"(c[3])
        : "r"(a[0]), "r"(a[1]), "r"(a[2]), "r"(a[3]), "r"(b[0]), "r"(b[1]));
}
__device__ __forceinline__ uint32_t pack_h2(float lo_elem, float hi_elem){
    return (uint32_t)__half_as_ushort(__float2half_rn(lo_elem))
         | ((uint32_t)__half_as_ushort(__float2half_rn(hi_elem)) << 16);
}

// ---------------- prep: W_hh fragments, fc_w fp16, zero h slot 1 + flags ----------------
__global__ void k_prep(const float* __restrict__ Whh, const float* __restrict__ fcw){
    int i = blockIdx.x * blockDim.x + threadIdx.x;
    if (i < HFRAG_E) g_fh[1][i] = __float2half(0.f);
    if (i < NCTA * 32) g_flag[i] = 0u;
    if (i < VV * HH) g_fcwh[i] = __float2half_rn(fcw[i]);
    if (i < NCTA * WFRAG_U4_PER_CTA){
        int cta = i / WFRAG_U4_PER_CTA;
        int j   = i % WFRAG_U4_PER_CTA;
        int kc  = j / 96;
        int j2  = j % 96;
        int nt  = j2 >> 5;
        int lane= j2 & 31;
        int lr = lane >> 2, lc = lane & 3;
        int n_local = nt * 8 + lr;
        int u = n_local >> 2, gate = n_local & 3;
        int grow = gate * HH + cta * UPC + u;
        const float* wr = Whh + (size_t)grow * HH + kc * 16;
        float w00 = wr[2*lc],     w01 = wr[2*lc + 1];
        float w10 = wr[2*lc + 8], w11 = wr[2*lc + 9];
        float h00 = __half2float(__float2half_rn(w00));
        float h01 = __half2float(__float2half_rn(w01));
        float h10 = __half2float(__float2half_rn(w10));
        float h11 = __half2float(__float2half_rn(w11));
        uint4 v;
        v.x = pack_h2(h00, h01);
        v.y = pack_h2(h10, h11);
        v.z = pack_h2(w00 - h00, w01 - h01);
        v.w = pack_h2(w10 - h10, w11 - h11);
        g_wfrag[i] = v;
    }
}

// ---------------- tf32 GEMM (proj only): C = A[M,K] @ B[N,K]^T + bias ----------------
__global__ __launch_bounds__(256) void k_gemm(
    const float* __restrict__ A, const float* __restrict__ Bm, float* __restrict__ C,
    int M, int N, int K, const float* __restrict__ bias1, const float* __restrict__ bias2)
{
    __shared__ float As[128][36];
    __shared__ float Bs[128][36];
    const int tid = threadIdx.x;
    const int w = tid >> 5, lane = tid & 31;
    const int lr = lane >> 2, lc = lane & 3;
    const int m0 = blockIdx.y * 128, n0 = blockIdx.x * 128;
    const int wm = (w >> 1) * 32, wn = (w & 1) * 64;
    float acc[2][8][4];
    #pragma unroll
    for (int i = 0; i < 2; i++)
        #pragma unroll
        for (int j = 0; j < 8; j++)
            #pragma unroll
            for (int q = 0; q < 4; q++) acc[i][j][q] = 0.f;
    float4 pa[4], pb[4];
    #pragma unroll
    for (int i = 0; i < 4; i++){
        int f = tid + i * 256; int r = f >> 3, cf = (f & 7) * 4;
        pa[i] = make_float4(0.f,0.f,0.f,0.f);
        if (m0 + r < M) pa[i] = *(const float4*)(A + (size_t)(m0 + r) * K + cf);
        pb[i] = make_float4(0.f,0.f,0.f,0.f);
        if (n0 + r < N) pb[i] = *(const float4*)(Bm + (size_t)(n0 + r) * K + cf);
    }
    for (int k0 = 0; k0 < K; k0 += 32){
        #pragma unroll
        for (int i = 0; i < 4; i++){
            int f = tid + i * 256; int r = f >> 3, cf = (f & 7) * 4;
            float4 ta = pa[i], tb = pb[i];
            As[r][cf+0] = to_tf32(ta.x); As[r][cf+1] = to_tf32(ta.y);
            As[r][cf+2] = to_tf32(ta.z); As[r][cf+3] = to_tf32(ta.w);
            Bs[r][cf+0] = to_tf32(tb.x); Bs[r][cf+1] = to_tf32(tb.y);
            Bs[r][cf+2] = to_tf32(tb.z); Bs[r][cf+3] = to_tf32(tb.w);
        }
        __syncthreads();
        int k1 = k0 + 32;
        if (k1 < K){
            #pragma unroll
            for (int i = 0; i < 4; i++){
                int f = tid + i * 256; int r = f >> 3, cf = (f & 7) * 4;
                pa[i] = make_float4(0.f,0.f,0.f,0.f);
                if (m0 + r < M) pa[i] = *(const float4*)(A + (size_t)(m0 + r) * K + k1 + cf);
                pb[i] = make_float4(0.f,0.f,0.f,0.f);
                if (n0 + r < N) pb[i] = *(const float4*)(Bm + (size_t)(n0 + r) * K + k1 + cf);
            }
        }
        #pragma unroll
        for (int kk = 0; kk < 32; kk += 8){
            uint32_t af[2][4], bf[8][2];
            #pragma unroll
            for (int mt = 0; mt < 2; mt++){
                int rb = wm + mt * 16;
                af[mt][0] = fu(As[rb + lr][kk + lc]);
                af[mt][1] = fu(As[rb + 8 + lr][kk + lc]);
                af[mt][2] = fu(As[rb + lr][kk + lc + 4]);
                af[mt][3] = fu(As[rb + 8 + lr][kk + lc + 4]);
            }
            #pragma unroll
            for (int nt = 0; nt < 8; nt++){
                int cb = wn + nt * 8;
                bf[nt][0] = fu(Bs[cb + lr][kk + lc]);
                bf[nt][1] = fu(Bs[cb + lr][kk + lc + 4]);
            }
            #pragma unroll
            for (int mt = 0; mt < 2; mt++)
                #pragma unroll
                for (int nt = 0; nt < 8; nt++)
                    mma_tf32(acc[mt][nt], af[mt], bf[nt]);
        }
        __syncthreads();
    }
    #pragma unroll
    for (int mt = 0; mt < 2; mt++)
        #pragma unroll
        for (int nt = 0; nt < 8; nt++){
            #pragma unroll
            for (int q = 0; q < 4; q++){
                int row = m0 + wm + mt * 16 + lr + (q >> 1) * 8;
                int col = n0 + wn + nt * 8 + lc * 2 + (q & 1);
                if (row < M && col < N){
                    float v = acc[mt][nt][q];
                    if (bias1) v += bias1[col];
                    if (bias2) v += bias2[col];
                    C[(size_t)row * N + col] = v;
                }
            }
        }
}

// ---------------- fp16 FC: out[b*512+t][v] = hall[t*64+b][:] @ fcw[v][:]^T + fc_b ----------------
__global__ __launch_bounds__(256) void k_fc(
    const __half* __restrict__ A, const __half* __restrict__ Bm,
    float* __restrict__ C, const float* __restrict__ bias)
{
    __shared__ __half As[128][56];
    __shared__ __half Bs[128][56];
    const int tid = threadIdx.x;
    const int w = tid >> 5, lane = tid & 31;
    const int lr = lane >> 2, lc = lane & 3;
    const int m0 = blockIdx.y * 128, n0 = blockIdx.x * 128;
    const int wm = (w >> 1) * 32, wn = (w & 1) * 64;
    float acc[2][8][4];
    #pragma unroll
    for (int i = 0; i < 2; i++)
        #pragma unroll
        for (int j = 0; j < 8; j++)
            #pragma unroll
            for (int q = 0; q < 4; q++) acc[i][j][q] = 0.f;

    uint4 pa[2], pb[2];
    #pragma unroll
    for (int i = 0; i < 2; i++){
        int f = tid + i * 256; int r = f >> 2, c8 = (f & 3) * 8;
        pa[i] = *(const uint4*)(A + (size_t)(m0 + r) * HH + c8);        // M=32768 exact
        pb[i] = make_uint4(0,0,0,0);
        if (n0 + r < VV) pb[i] = *(const uint4*)(Bm + (size_t)(n0 + r) * HH + c8);
    }
    for (int k0 = 0; k0 < HH; k0 += 32){
        #pragma unroll
        for (int i = 0; i < 2; i++){
            int f = tid + i * 256; int r = f >> 2, c8 = (f & 3) * 8;
            *(uint4*)&As[r][c8] = pa[i];
            *(uint4*)&Bs[r][c8] = pb[i];
        }
        __syncthreads();
        int k1 = k0 + 32;
        if (k1 < HH){
            #pragma unroll
            for (int i = 0; i < 2; i++){
                int f = tid + i * 256; int r = f >> 2, c8 = (f & 3) * 8;
                pa[i] = *(const uint4*)(A + (size_t)(m0 + r) * HH + k1 + c8);
                pb[i] = make_uint4(0,0,0,0);
                if (n0 + r < VV) pb[i] = *(const uint4*)(Bm + (size_t)(n0 + r) * HH + k1 + c8);
            }
        }
        #pragma unroll
        for (int kk = 0; kk < 32; kk += 16){
            uint32_t af[2][4], bf[8][2];
            #pragma unroll
            for (int mt = 0; mt < 2; mt++){
                int rb = wm + mt * 16;
                af[mt][0] = *(const uint32_t*)&As[rb + lr][kk + 2*lc];
                af[mt][1] = *(const uint32_t*)&As[rb + 8 + lr][kk + 2*lc];
                af[mt][2] = *(const uint32_t*)&As[rb + lr][kk + 8 + 2*lc];
                af[mt][3] = *(const uint32_t*)&As[rb + 8 + lr][kk + 8 + 2*lc];
            }
            #pragma unroll
            for (int nt = 0; nt < 8; nt++){
                int cb = wn + nt * 8;
                bf[nt][0] = *(const uint32_t*)&Bs[cb + lr][kk + 2*lc];
                bf[nt][1] = *(const uint32_t*)&Bs[cb + lr][kk + 8 + 2*lc];
            }
            #pragma unroll
            for (int mt = 0; mt < 2; mt++)
                #pragma unroll
                for (int nt = 0; nt < 8; nt++)
                    mma_fp16(acc[mt][nt], af[mt], bf[nt]);
        }
        __syncthreads();
    }
    #pragma unroll
    for (int mt = 0; mt < 2; mt++)
        #pragma unroll
        for (int nt = 0; nt < 8; nt++){
            #pragma unroll
            for (int q = 0; q < 4; q++){
                int row = m0 + wm + mt * 16 + lr + (q >> 1) * 8;
                int col = n0 + wn + nt * 8 + lc * 2 + (q & 1);
                if (col < VV){
                    int t = row >> 6, b = row & 63;
                    C[(size_t)(b * TT + t) * VV + col] = acc[mt][nt][q] + bias[col];
                }
            }
        }
}

// ---------------- persistent LSTM recurrence (fp16 2-product, flag barrier) ----------------
__global__ __launch_bounds__(128, 1) void k_persist(const int* __restrict__ x)
{
    extern __shared__ float sm[];
    uint4* Bsm = (uint4*)sm;                 // 4608 uint4 = 73728 B
    float*  gs = sm + 4*WFRAG_U4_PER_CTA;    // 64 x 25 floats
    const int tid  = threadIdx.x;
    const int w    = tid >> 5, lane = tid & 31;
    const int lr   = lane >> 2, lc2 = (lane & 3) * 2;
    const int cta  = blockIdx.x;

    // persistent weight slice -> smem
    {
        const uint4* wsrc = g_wfrag + (size_t)cta * WFRAG_U4_PER_CTA;
        for (int i = tid; i < WFRAG_U4_PER_CTA; i += 128) Bsm[i] = wsrc[i];
    }

    // epilogue work items: 3 per thread -> (b, u); 384 items
    int eb[3], eu[3]; float creg[3];
    const int* xp[3];
    #pragma unroll
    for (int j = 0; j < 3; j++){
        int idx = tid + j * 128;
        eb[j] = idx & 63; eu[j] = idx >> 6;
        creg[j] = 0.f;
        xp[j] = x + eb[j] * TT;
    }
    unsigned genreg;
    asm volatile("ld.volatile.global.u32 %0, [%1];" : "=r"(genreg) : "l"(&g_gen));
    __syncthreads();

    for (int t = 0; t < TT; t++){
        const uint4* Ah = (const uint4*)g_fh[(t + 1) & 1];   // slot (t-1)&1; t=0 -> zeroed slot 1

        float accH[3][4], accL[3][4];
        #pragma unroll
        for (int n = 0; n < 3; n++)
            #pragma unroll
            for (int q = 0; q < 4; q++){ accH[n][q] = 0.f; accL[n][q] = 0.f; }

        // 8-deep A-fragment prefetch ring (issued first: feeds mma immediately)
        uint4 ahb[8];
        #pragma unroll
        for (int j = 0; j < 8; j++)
            ahb[j] = __ldg(Ah + (j * 4 + w) * 32 + lane);
        uint4 bcur[3], bnxt[3];
        #pragma unroll
        for (int nt = 0; nt < 3; nt++) bcur[nt] = Bsm[nt * 32 + lane];

        // proj gate biases for the epilogue (hidden behind GEMM)
        float pv[3][4];
        #pragma unroll
        for (int j = 0; j < 3; j++){
            int xv = __ldg(xp[j] + t);
            const float* pr = g_proj + (size_t)xv * G4 + (cta * UPC + eu[j]);
            #pragma unroll
            for (int g = 0; g < 4; g++) pv[j][g] = __ldg(pr + g * HH);
        }

        for (int c = 0; c < 6; c++){
            #pragma unroll
            for (int j = 0; j < 8; j++){
                int kc = c * 8 + j;
                uint4 a4 = ahb[j];
                int kn = kc + 8;
                if (kn < NKC)
                    ahb[j] = __ldg(Ah + (kn * 4 + w) * 32 + lane);
                if (kc + 1 < NKC){
                    #pragma unroll
                    for (int nt = 0; nt < 3; nt++)
                        bnxt[nt] = Bsm[((kc + 1) * 3 + nt) * 32 + lane];
                }
                uint32_t ah[4] = {a4.x, a4.y, a4.z, a4.w};
                #pragma unroll
                for (int nt = 0; nt < 3; nt++){
                    uint32_t bh[2] = {bcur[nt].x, bcur[nt].y};
                    uint32_t bl[2] = {bcur[nt].z, bcur[nt].w};
                    mma_fp16(accH[nt], ah, bh);
                    mma_fp16(accL[nt], ah, bl);
                }
                #pragma unroll
                for (int nt = 0; nt < 3; nt++) bcur[nt] = bnxt[nt];
            }
        }

        // gate tile -> smem
        #pragma unroll
        for (int nt = 0; nt < 3; nt++){
            #pragma unroll
            for (int q = 0; q < 4; q++){
                int row = w * 16 + lr + (q >> 1) * 8;
                int col = nt * 8 + lc2 + (q & 1);
                gs[row * 25 + col] = accH[nt][q] + accL[nt][q];
            }
        }
        __syncthreads();

        // pointwise LSTM + h scatter (fp16 hall for FC, A-fragment fp16 for next step)
        __half* hdst = g_fh[t & 1];
        __half* hall_t = g_hallh + (size_t)t * (BB * HH);
        #pragma unroll
        for (int j = 0; j < 3; j++){
            int b = eb[j], u = eu[j], ug = cta * UPC + u;
            float gi = gs[b * 25 + 4*u + 0] + pv[j][0];
            float gf = gs[b * 25 + 4*u + 1] + pv[j][1];
            float gg = gs[b * 25 + 4*u + 2] + pv[j][2];
            float go = gs[b * 25 + 4*u + 3] + pv[j][3];
            float si = 1.f / (1.f + expf(-gi));
            float sf = 1.f / (1.f + expf(-gf));
            float so = 1.f / (1.f + expf(-go));
            float cnew = sf * creg[j] + si * tanhf(gg);
            float hnew = so * tanhf(cnew);
            creg[j] = cnew;
            __half hb = __float2half_rn(hnew);
            hall_t[b * HH + ug] = hb;
            // A-fragment scatter (verified R9/R13)
            int kc = ug >> 4, kk = ug & 15;
            int r = b & 15, wb = b >> 4;
            int lane_h = (r & 7) * 4 + ((kk & 7) >> 1);
            int reg = (r >> 3) + 2 * (kk >> 3);
            int half = kk & 1;
            int elem = (((kc * 4 + wb) * 32 + lane_h) * 4 + reg) * 2 + half;
            hdst[elem] = hb;
        }

        // ---- contention-free grid barrier: parallel flags + single relay ----
        __threadfence();
        __syncthreads();
        genreg += 1;
        if (tid == 0)
            asm volatile("st.release.gpu.global.u32 [%0], %1;"
                :: "l"(&g_flag[cta * 32]), "r"(genreg) : "memory");
        if (cta == 0 && w == 0){
            unsigned f0, f1, f2, f3; unsigned ok;
            do {
                asm volatile("ld.acquire.gpu.global.u32 %0, [%1];" : "=r"(f0) : "l"(&g_flag[lane * 32]));
                asm volatile("ld.acquire.gpu.global.u32 %0, [%1];" : "=r"(f1) : "l"(&g_flag[(lane + 32) * 32]));
                asm volatile("ld.acquire.gpu.global.u32 %0, [%1];" : "=r"(f2) : "l"(&g_flag[(lane + 64) * 32]));
                asm volatile("ld.acquire.gpu.global.u32 %0, [%1];" : "=r"(f3) : "l"(&g_flag[(lane + 96) * 32]));
                ok = ((int)(f0 - genreg) >= 0) && ((int)(f1 - genreg) >= 0)
                  && ((int)(f2 - genreg) >= 0) && ((int)(f3 - genreg) >= 0);
            } while (__ballot_sync(0xffffffffu, ok) != 0xffffffffu);
            if (lane == 0)
                asm volatile("st.release.gpu.global.u32 [%0], %1;" :: "l"(&g_gen), "r"(genreg) : "memory");
        }
        if (tid == 0){
            unsigned cur;
            do {
                asm volatile("ld.acquire.gpu.global.u32 %0, [%1];" : "=r"(cur) : "l"(&g_gen));
            } while ((int)(cur - genreg) < 0);
        }
        __syncthreads();
    }
}

// ---------------- host launch ----------------
extern "C" void kernel_launch(void* const* d_in, const int* in_sizes, int n_in,
                              void* d_out, int out_size)
{
    const int* x = 0;
    const float *embed = 0, *W_ih = 0, *W_hh = 0, *b_ih = 0, *b_hh = 0, *fc_w = 0, *fc_b = 0;
    for (int i = 0; i < n_in; i++){
        switch (in_sizes[i]){
            case BB*TT:      x     = (const int*)  d_in[i]; break;
            case VV*EE:      embed = (const float*)d_in[i]; break;
            case G4*EE:      W_ih  = (const float*)d_in[i]; break;
            case G4*HH:      W_hh  = (const float*)d_in[i]; break;
            case G4:         if (!b_ih) b_ih = (const float*)d_in[i];
                             else        b_hh = (const float*)d_in[i]; break;
            case VV*HH:      fc_w  = (const float*)d_in[i]; break;
            case VV:         fc_b  = (const float*)d_in[i]; break;
            default: break;  // truncate_length — identity in forward pass
        }
    }
    float* out = (float*)d_out;

    float* p_proj = 0; __half* p_hall = 0; __half* p_fcw = 0;
    cudaGetSymbolAddress((void**)&p_proj, g_proj);
    cudaGetSymbolAddress((void**)&p_hall, g_hallh);
    cudaGetSymbolAddress((void**)&p_fcw, g_fcwh);

    const int SMEM = WFRAG_U4_PER_CTA * 16 + 64 * 25 * 4;   // 73728 + 6400 = 80128
    cudaFuncSetAttribute(k_persist, cudaFuncAttributeMaxDynamicSharedMemorySize, SMEM);

    // 1) prep: W_hh fragments + fc_w fp16 + zero h slot 1 + flags (replay-safe)
    {
        int n = VV * HH;   // 3,840,000 covers all prep ranges
        k_prep<<<(n + 255) / 256, 256>>>(W_hh, fc_w);
    }
    // 2) proj[V,4H] = embed @ W_ih^T + b_ih + b_hh  (tf32)
    {
        dim3 grid(G4 / 128, (VV + 127) / 128);
        k_gemm<<<grid, 256>>>(embed, W_ih, p_proj, VV, G4, EE, b_ih, b_hh);
    }
    // 3) persistent recurrence: 512 steps, 1 launch
    k_persist<<<NCTA, 128, SMEM>>>(x);
    // 4) out[B,T,V] = hall(fp16) @ fc_w(fp16)^T + fc_b
    {
        dim3 grid((VV + 127) / 128, (BB * TT) / 128);
        k_fc<<<grid, 256>>>(p_hall, p_fcw, out, fc_b);
    }
}

// round 15
// speedup vs baseline: 1.2962x; 1.2049x over previous
#include <cuda_runtime.h>
#include <cuda_fp16.h>
#include <cstdint>
#include <math.h>

#define BB 64
#define TT 512
#define EE 256
#define HH 768
#define G4 3072
#define VV 5000

#define NCTA 128          // persistent CTAs, 6 hidden units each
#define UPC  6
#define NKC  48           // K=768 / 16 (fp16 mma k16 chunks)
#define WFRAG_U4_PER_CTA (NKC*3*32)     // 4608 uint4 per CTA (W_hh fp16 hi/lo packed)
#define HFRAG_E 49152                   // 64*768 fp16 elements per slot
#define NVT 625                         // 5000/8 vocab n-tiles (125 CTAs x 5)
#define FCF_U2 (NVT*NKC*32)             // 960000 uint2

// ---------------- device scratch ----------------
__device__ float g_proj[(size_t)VV * G4];                 // embed@W_ih^T + biases
__device__ __align__(16) uint4 g_wfrag[(size_t)NCTA * WFRAG_U4_PER_CTA];
__device__ __align__(16) __half g_hfrag[(size_t)513 * HFRAG_E]; // h A-fragments per t; slot 512 = zeros
__device__ __align__(16) uint2 g_fcfrag[(size_t)FCF_U2]; // fc_w B-fragments fp16
__device__ unsigned g_flag[NCTA * 32];                    // arrival flags, 128B-spaced

__device__ __forceinline__ float to_tf32(float x){
    uint32_t u; asm("cvt.rna.tf32.f32 %0, %1;" : "=r"(u) : "f"(x));
    return __uint_as_float(u);
}
__device__ __forceinline__ uint32_t fu(float x){ return __float_as_uint(x); }
__device__ __forceinline__ void mma_tf32(float* c, const uint32_t* a, const uint32_t* b){
    asm volatile("mma.sync.aligned.m16n8k8.row.col.f32.tf32.tf32.f32 "
        "{%0,%1,%2,%3}, {%4,%5,%6,%7}, {%8,%9}, {%0,%1,%2,%3};"
        : "+f"(c[0]), "+f"(c[1]), "+f"(c[2]), "+f"(c[3])
        : "r"(a[0]), "r"(a[1]), "r"(a[2]), "r"(a[3]), "r"(b[0]), "r"(b[1]));
}
__device__ __forceinline__ void mma_fp16(float* c, const uint32_t* a, uint32_t b0, uint32_t b1){
    asm volatile("mma.sync.aligned.m16n8k16.row.col.f32.f16.f16.f32 "
        "{%0,%1,%2,%3}, {%4,%5,%6,%7}, {%8,%9}, {%0,%1,%2,%3};"
        : "+f"(c[0]), "+f"(c[1]), "+f"(c[2]), "+f"(c[3])
        : "r"(a[0]), "r"(a[1]), "r"(a[2]), "r"(a[3]), "r"(b0), "r"(b1));
}
__device__ __forceinline__ uint32_t pack_h2(float lo_elem, float hi_elem){
    return (uint32_t)__half_as_ushort(__float2half_rn(lo_elem))
         | ((uint32_t)__half_as_ushort(__float2half_rn(hi_elem)) << 16);
}
// fast sigmoid/tanh via MUFU (err ~2^-21)
__device__ __forceinline__ float fsig(float x){
    float e; asm("ex2.approx.ftz.f32 %0, %1;" : "=f"(e) : "f"(-1.4426950408889634f * x));
    float r; asm("rcp.approx.ftz.f32 %0, %1;" : "=f"(r) : "f"(1.f + e));
    return r;
}
__device__ __forceinline__ float ftanh(float x){ return 2.f * fsig(2.f * x) - 1.f; }

// ---------------- prep ----------------
__global__ void k_prep(const float* __restrict__ Whh, const float* __restrict__ fcw){
    int i = blockIdx.x * blockDim.x + threadIdx.x;
    if (i < HFRAG_E) g_hfrag[(size_t)512 * HFRAG_E + i] = __float2half(0.f);
    if (i < NCTA * 32) g_flag[i] = 0u;
    if (i < FCF_U2){
        int vt = i / 1536, r = i % 1536, kc = r / 32, lane = r & 31;
        int col = vt * 8 + (lane >> 2);
        const float* wr = fcw + (size_t)col * HH + kc * 16 + 2 * (lane & 3);
        uint2 v;
        v.x = pack_h2(wr[0], wr[1]);
        v.y = pack_h2(wr[8], wr[9]);
        g_fcfrag[i] = v;
    }
    if (i < NCTA * WFRAG_U4_PER_CTA){
        int cta = i / WFRAG_U4_PER_CTA;
        int j   = i % WFRAG_U4_PER_CTA;
        int kc  = j / 96, j2 = j % 96, nt = j2 >> 5, lane = j2 & 31;
        int lr = lane >> 2, lc = lane & 3;
        int n_local = nt * 8 + lr;
        int u = n_local >> 2, gate = n_local & 3;
        int grow = gate * HH + cta * UPC + u;
        const float* wr = Whh + (size_t)grow * HH + kc * 16;
        float w00 = wr[2*lc],     w01 = wr[2*lc + 1];
        float w10 = wr[2*lc + 8], w11 = wr[2*lc + 9];
        float h00 = __half2float(__float2half_rn(w00));
        float h01 = __half2float(__float2half_rn(w01));
        float h10 = __half2float(__float2half_rn(w10));
        float h11 = __half2float(__float2half_rn(w11));
        uint4 v;
        v.x = pack_h2(h00, h01);
        v.y = pack_h2(h10, h11);
        v.z = pack_h2(w00 - h00, w01 - h01);
        v.w = pack_h2(w10 - h10, w11 - h11);
        g_wfrag[i] = v;
    }
}

// ---------------- tf32 GEMM (proj): C = A[M,K] @ B[N,K]^T + bias1 + bias2 ----------------
__global__ __launch_bounds__(256) void k_gemm(
    const float* __restrict__ A, const float* __restrict__ Bm, float* __restrict__ C,
    int M, int N, int K, const float* __restrict__ bias1, const float* __restrict__ bias2)
{
    __shared__ float As[128][36];
    __shared__ float Bs[128][36];
    const int tid = threadIdx.x;
    const int w = tid >> 5, lane = tid & 31;
    const int lr = lane >> 2, lc = lane & 3;
    const int m0 = blockIdx.y * 128, n0 = blockIdx.x * 128;
    const int wm = (w >> 1) * 32, wn = (w & 1) * 64;
    float acc[2][8][4];
    #pragma unroll
    for (int i = 0; i < 2; i++)
        #pragma unroll
        for (int j = 0; j < 8; j++)
            #pragma unroll
            for (int q = 0; q < 4; q++) acc[i][j][q] = 0.f;
    float4 pa[4], pb[4];
    #pragma unroll
    for (int i = 0; i < 4; i++){
        int f = tid + i * 256; int r = f >> 3, cf = (f & 7) * 4;
        pa[i] = make_float4(0.f,0.f,0.f,0.f);
        if (m0 + r < M) pa[i] = *(const float4*)(A + (size_t)(m0 + r) * K + cf);
        pb[i] = make_float4(0.f,0.f,0.f,0.f);
        if (n0 + r < N) pb[i] = *(const float4*)(Bm + (size_t)(n0 + r) * K + cf);
    }
    for (int k0 = 0; k0 < K; k0 += 32){
        #pragma unroll
        for (int i = 0; i < 4; i++){
            int f = tid + i * 256; int r = f >> 3, cf = (f & 7) * 4;
            float4 ta = pa[i], tb = pb[i];
            As[r][cf+0] = to_tf32(ta.x); As[r][cf+1] = to_tf32(ta.y);
            As[r][cf+2] = to_tf32(ta.z); As[r][cf+3] = to_tf32(ta.w);
            Bs[r][cf+0] = to_tf32(tb.x); Bs[r][cf+1] = to_tf32(tb.y);
            Bs[r][cf+2] = to_tf32(tb.z); Bs[r][cf+3] = to_tf32(tb.w);
        }
        __syncthreads();
        int k1 = k0 + 32;
        if (k1 < K){
            #pragma unroll
            for (int i = 0; i < 4; i++){
                int f = tid + i * 256; int r = f >> 3, cf = (f & 7) * 4;
                pa[i] = make_float4(0.f,0.f,0.f,0.f);
                if (m0 + r < M) pa[i] = *(const float4*)(A + (size_t)(m0 + r) * K + k1 + cf);
                pb[i] = make_float4(0.f,0.f,0.f,0.f);
                if (n0 + r < N) pb[i] = *(const float4*)(Bm + (size_t)(n0 + r) * K + k1 + cf);
            }
        }
        #pragma unroll
        for (int kk = 0; kk < 32; kk += 8){
            uint32_t af[2][4], bf[8][2];
            #pragma unroll
            for (int mt = 0; mt < 2; mt++){
                int rb = wm + mt * 16;
                af[mt][0] = fu(As[rb + lr][kk + lc]);
                af[mt][1] = fu(As[rb + 8 + lr][kk + lc]);
                af[mt][2] = fu(As[rb + lr][kk + lc + 4]);
                af[mt][3] = fu(As[rb + 8 + lr][kk + lc + 4]);
            }
            #pragma unroll
            for (int nt = 0; nt < 8; nt++){
                int cb = wn + nt * 8;
                bf[nt][0] = fu(Bs[cb + lr][kk + lc]);
                bf[nt][1] = fu(Bs[cb + lr][kk + lc + 4]);
            }
            #pragma unroll
            for (int mt = 0; mt < 2; mt++)
                #pragma unroll
                for (int nt = 0; nt < 8; nt++)
                    mma_tf32(acc[mt][nt], af[mt], bf[nt]);
        }
        __syncthreads();
    }
    #pragma unroll
    for (int mt = 0; mt < 2; mt++)
        #pragma unroll
        for (int nt = 0; nt < 8; nt++){
            #pragma unroll
            for (int q = 0; q < 4; q++){
                int row = m0 + wm + mt * 16 + lr + (q >> 1) * 8;
                int col = n0 + wn + nt * 8 + lc * 2 + (q & 1);
                if (row < M && col < N){
                    float v = acc[mt][nt][q];
                    if (bias1) v += bias1[col];
                    if (bias2) v += bias2[col];
                    C[(size_t)row * N + col] = v;
                }
            }
        }
}

// ---------------- persistent: recurrence + fused FC ----------------
// 128 CTAs x 128 thr. Per step t: one A-fragment stream of h(t-1) feeds
// gates (3 nt, W hi+lo) AND FC out[:, t-1, cta's 40 vocab cols] (5 nt).
__global__ __launch_bounds__(128, 1) void k_persist(const int* __restrict__ x,
                                                    float* __restrict__ out,
                                                    const float* __restrict__ fcb)
{
    extern __shared__ char smraw[];
    uint4* Bsm = (uint4*)smraw;                         // 73728 B
    uint2* Fsm = (uint2*)(smraw + WFRAG_U4_PER_CTA*16); // 61440 B
    float* gs  = (float*)(smraw + WFRAG_U4_PER_CTA*16 + 61440); // 6400 B
    const int tid  = threadIdx.x;
    const int w    = tid >> 5, lane = tid & 31;
    const int lr   = lane >> 2, lc2 = (lane & 3) * 2;
    const int cta  = blockIdx.x;
    const bool has_fc = (cta < 125);

    {   // persistent weights -> smem
        const uint4* wsrc = g_wfrag + (size_t)cta * WFRAG_U4_PER_CTA;
        for (int i = tid; i < WFRAG_U4_PER_CTA; i += 128) Bsm[i] = wsrc[i];
        if (has_fc){
            const uint2* fsrc = g_fcfrag + (size_t)cta * 5 * NKC * 32;
            for (int i = tid; i < 5 * NKC * 32; i += 128) Fsm[i] = fsrc[i];
        }
    }

    // FC bias regs: vtl in [0,5): cols (cta*5+vtl)*8 + lc2 + {0,1}
    float bv[5][2];
    #pragma unroll
    for (int v = 0; v < 5; v++){
        int col = (cta * 5 + v) * 8 + lc2;
        bv[v][0] = has_fc ? fcb[col] : 0.f;
        bv[v][1] = has_fc ? fcb[col + 1] : 0.f;
    }

    // epilogue items: 3 per thread -> (b, u)
    int eb[3], eu[3]; float creg[3]; const int* xp[3];
    #pragma unroll
    for (int j = 0; j < 3; j++){
        int idx = tid + j * 128;
        eb[j] = idx & 63; eu[j] = idx >> 6;
        creg[j] = 0.f;
        xp[j] = x + eb[j] * TT;
    }
    // pv for t=0
    float pv[3][4];
    #pragma unroll
    for (int j = 0; j < 3; j++){
        int xv = __ldg(xp[j]);
        const float* pr = g_proj + (size_t)xv * G4 + (cta * UPC + eu[j]);
        #pragma unroll
        for (int g = 0; g < 4; g++) pv[j][g] = __ldg(pr + g * HH);
    }
    unsigned genreg = 0;
    __syncthreads();

    for (int t = 0; t < TT; t++){
        const __half* hsl = g_hfrag + (size_t)((t == 0) ? 512 : (t - 1)) * HFRAG_E;
        const uint4* Ah = (const uint4*)hsl;

        float accH[3][4], accL[3][4], accF[5][4];
        #pragma unroll
        for (int n = 0; n < 3; n++)
            #pragma unroll
            for (int q = 0; q < 4; q++){ accH[n][q] = 0.f; accL[n][q] = 0.f; }
        #pragma unroll
        for (int n = 0; n < 5; n++)
            #pragma unroll
            for (int q = 0; q < 4; q++) accF[n][q] = 0.f;

        uint4 ahb[8];
        #pragma unroll
        for (int j = 0; j < 8; j++)
            ahb[j] = __ldg(Ah + (j * 4 + w) * 32 + lane);

        for (int c = 0; c < 6; c++){
            #pragma unroll
            for (int j = 0; j < 8; j++){
                int kc = c * 8 + j;
                uint4 a4 = ahb[j];
                if (kc + 8 < NKC)
                    ahb[j] = __ldg(Ah + ((kc + 8) * 4 + w) * 32 + lane);
                uint32_t ah[4] = {a4.x, a4.y, a4.z, a4.w};
                #pragma unroll
                for (int nt = 0; nt < 3; nt++){
                    uint4 bb = Bsm[(kc * 3 + nt) * 32 + lane];
                    mma_fp16(accH[nt], ah, bb.x, bb.y);
                    mma_fp16(accL[nt], ah, bb.z, bb.w);
                }
                #pragma unroll
                for (int v = 0; v < 5; v++){
                    uint2 f2 = Fsm[(v * NKC + kc) * 32 + lane];
                    mma_fp16(accF[v], ah, f2.x, f2.y);
                }
            }
        }

        // FC store for tfc = t-1 (skip t==0: operand was zeros)
        if (has_fc && t > 0){
            int tfc = t - 1;
            #pragma unroll
            for (int v = 0; v < 5; v++){
                #pragma unroll
                for (int q = 0; q < 4; q++){
                    int b = w * 16 + lr + (q >> 1) * 8;
                    int col = (cta * 5 + v) * 8 + lc2 + (q & 1);
                    out[(size_t)(b * TT + tfc) * VV + col] = accF[v][q] + bv[v][q & 1];
                }
            }
        }

        // gate tile -> smem
        #pragma unroll
        for (int nt = 0; nt < 3; nt++){
            #pragma unroll
            for (int q = 0; q < 4; q++){
                int row = w * 16 + lr + (q >> 1) * 8;
                int col = nt * 8 + lc2 + (q & 1);
                gs[row * 25 + col] = accH[nt][q] + accL[nt][q];
            }
        }
        __syncthreads();

        // pointwise LSTM + h A-fragment scatter into slot t
        __half* hdst = g_hfrag + (size_t)t * HFRAG_E;
        #pragma unroll
        for (int j = 0; j < 3; j++){
            int b = eb[j], u = eu[j], ug = cta * UPC + u;
            float gi = gs[b * 25 + 4*u + 0] + pv[j][0];
            float gf = gs[b * 25 + 4*u + 1] + pv[j][1];
            float gg = gs[b * 25 + 4*u + 2] + pv[j][2];
            float go = gs[b * 25 + 4*u + 3] + pv[j][3];
            float cnew = fsig(gf) * creg[j] + fsig(gi) * ftanh(gg);
            float hnew = fsig(go) * ftanh(cnew);
            creg[j] = cnew;
            int kc = ug >> 4, kk = ug & 15;
            int r = b & 15, wb = b >> 4;
            int lane_h = (r & 7) * 4 + ((kk & 7) >> 1);
            int reg = (r >> 3) + 2 * (kk >> 3);
            int half = kk & 1;
            int elem = (((kc * 4 + wb) * 32 + lane_h) * 4 + reg) * 2 + half;
            hdst[elem] = __float2half_rn(hnew);
        }

        // arrive, prefetch next pv, flat-poll all flags
        __threadfence();
        __syncthreads();
        genreg += 1;
        if (tid == 0)
            asm volatile("st.release.gpu.global.u32 [%0], %1;"
                :: "l"(&g_flag[cta * 32]), "r"(genreg) : "memory");
        if (t + 1 < TT){
            #pragma unroll
            for (int j = 0; j < 3; j++){
                int xv = __ldg(xp[j] + t + 1);
                const float* pr = g_proj + (size_t)xv * G4 + (cta * UPC + eu[j]);
                #pragma unroll
                for (int g = 0; g < 4; g++) pv[j][g] = __ldg(pr + g * HH);
            }
        }
        if (tid < 32){
            unsigned f0, f1, f2, f3; unsigned ok;
            do {
                asm volatile("ld.acquire.gpu.global.u32 %0, [%1];" : "=r"(f0) : "l"(&g_flag[lane * 32]));
                asm volatile("ld.acquire.gpu.global.u32 %0, [%1];" : "=r"(f1) : "l"(&g_flag[(lane + 32) * 32]));
                asm volatile("ld.acquire.gpu.global.u32 %0, [%1];" : "=r"(f2) : "l"(&g_flag[(lane + 64) * 32]));
                asm volatile("ld.acquire.gpu.global.u32 %0, [%1];" : "=r"(f3) : "l"(&g_flag[(lane + 96) * 32]));
                ok = ((int)(f0 - genreg) >= 0) && ((int)(f1 - genreg) >= 0)
                  && ((int)(f2 - genreg) >= 0) && ((int)(f3 - genreg) >= 0);
            } while (__ballot_sync(0xffffffffu, ok) != 0xffffffffu);
        }
        __syncthreads();
    }

    // tail: FC for t = 511 (h(511) visible after final barrier)
    if (has_fc){
        const uint4* Ah = (const uint4*)(g_hfrag + (size_t)511 * HFRAG_E);
        float accF[5][4];
        #pragma unroll
        for (int n = 0; n < 5; n++)
            #pragma unroll
            for (int q = 0; q < 4; q++) accF[n][q] = 0.f;
        for (int kc = 0; kc < NKC; kc++){
            uint4 a4 = __ldg(Ah + (kc * 4 + w) * 32 + lane);
            uint32_t ah[4] = {a4.x, a4.y, a4.z, a4.w};
            #pragma unroll
            for (int v = 0; v < 5; v++){
                uint2 f2 = Fsm[(v * NKC + kc) * 32 + lane];
                mma_fp16(accF[v], ah, f2.x, f2.y);
            }
        }
        #pragma unroll
        for (int v = 0; v < 5; v++){
            #pragma unroll
            for (int q = 0; q < 4; q++){
                int b = w * 16 + lr + (q >> 1) * 8;
                int col = (cta * 5 + v) * 8 + lc2 + (q & 1);
                out[(size_t)(b * TT + 511) * VV + col] = accF[v][q] + bv[v][q & 1];
            }
        }
    }
}

// ---------------- host launch ----------------
extern "C" void kernel_launch(void* const* d_in, const int* in_sizes, int n_in,
                              void* d_out, int out_size)
{
    const int* x = 0;
    const float *embed = 0, *W_ih = 0, *W_hh = 0, *b_ih = 0, *b_hh = 0, *fc_w = 0, *fc_b = 0;
    for (int i = 0; i < n_in; i++){
        switch (in_sizes[i]){
            case BB*TT:      x     = (const int*)  d_in[i]; break;
            case VV*EE:      embed = (const float*)d_in[i]; break;
            case G4*EE:      W_ih  = (const float*)d_in[i]; break;
            case G4*HH:      W_hh  = (const float*)d_in[i]; break;
            case G4:         if (!b_ih) b_ih = (const float*)d_in[i];
                             else        b_hh = (const float*)d_in[i]; break;
            case VV*HH:      fc_w  = (const float*)d_in[i]; break;
            case VV:         fc_b  = (const float*)d_in[i]; break;
            default: break;  // truncate_length — identity in forward pass
        }
    }
    float* out = (float*)d_out;
    float* p_proj = 0;
    cudaGetSymbolAddress((void**)&p_proj, g_proj);

    const int SMEM = WFRAG_U4_PER_CTA * 16 + 61440 + 64 * 25 * 4;  // 141568
    cudaFuncSetAttribute(k_persist, cudaFuncAttributeMaxDynamicSharedMemorySize, SMEM);

    // 1) prep: W_hh + fc_w fragments, zero h slot 512 + flags (replay-safe)
    {
        int n = FCF_U2;   // 960000 covers all prep ranges
        k_prep<<<(n + 255) / 256, 256>>>(W_hh, fc_w);
    }
    // 2) proj[V,4H] = embed @ W_ih^T + b_ih + b_hh  (tf32)
    {
        dim3 grid(G4 / 128, (VV + 127) / 128);
        k_gemm<<<grid, 256>>>(embed, W_ih, p_proj, VV, G4, EE, b_ih, b_hh);
    }
    // 3) persistent recurrence + fused FC: 1 launch
    k_persist<<<NCTA, 128, SMEM>>>(x, out, fc_b);
}

// round 16
// speedup vs baseline: 1.6546x; 1.2765x over previous
#include <cuda_runtime.h>
#include <cuda_fp16.h>
#include <cstdint>
#include <math.h>

#define BB 64
#define TT 512
#define EE 256
#define HH 768
#define G4 3072
#define VV 5000

#define NCTA 128          // persistent CTAs, 6 hidden units each
#define UPC  6
#define NKC  48           // K=768 / 16 (fp16 mma k16 chunks)
#define WFRAG_U4_PER_CTA (NKC*3*32)     // 4608 uint4 per CTA (W_hh fp16 hi/lo packed)
#define HFRAG_E 49152                   // 64*768 fp16 elements per slot
#define NVT 625                         // 5000/8 vocab n-tiles (125 CTAs x 5)
#define FCF_U2 (NVT*NKC*32)             // 960000 uint2

// ---------------- device scratch ----------------
__device__ float g_proj[(size_t)VV * G4];                 // embed@W_ih^T + biases
__device__ __align__(16) uint4 g_wfrag[(size_t)NCTA * WFRAG_U4_PER_CTA];
__device__ __align__(16) __half g_hfrag[(size_t)513 * HFRAG_E]; // h A-fragments per t; slot 512 = zeros
__device__ __align__(16) uint2 g_fcfrag[(size_t)FCF_U2]; // fc_w B-fragments fp16
__device__ unsigned g_flag[NCTA * 32];                    // arrival flags, 128B-spaced

__device__ __forceinline__ float to_tf32(float x){
    uint32_t u; asm("cvt.rna.tf32.f32 %0, %1;" : "=r"(u) : "f"(x));
    return __uint_as_float(u);
}
__device__ __forceinline__ uint32_t fu(float x){ return __float_as_uint(x); }
__device__ __forceinline__ void mma_tf32(float* c, const uint32_t* a, const uint32_t* b){
    asm volatile("mma.sync.aligned.m16n8k8.row.col.f32.tf32.tf32.f32 "
        "{%0,%1,%2,%3}, {%4,%5,%6,%7}, {%8,%9}, {%0,%1,%2,%3};"
        : "+f"(c[0]), "+f"(c[1]), "+f"(c[2]), "+f"(c[3])
        : "r"(a[0]), "r"(a[1]), "r"(a[2]), "r"(a[3]), "r"(b[0]), "r"(b[1]));
}
__device__ __forceinline__ void mma_fp16(float* c, const uint32_t* a, uint32_t b0, uint32_t b1){
    asm volatile("mma.sync.aligned.m16n8k16.row.col.f32.f16.f16.f32 "
        "{%0,%1,%2,%3}, {%4,%5,%6,%7}, {%8,%9}, {%0,%1,%2,%3};"
        : "+f"(c[0]), "+f"(c[1]), "+f"(c[2]), "+f"(c[3])
        : "r"(a[0]), "r"(a[1]), "r"(a[2]), "r"(a[3]), "r"(b0), "r"(b1));
}
__device__ __forceinline__ uint32_t pack_h2(float lo_elem, float hi_elem){
    return (uint32_t)__half_as_ushort(__float2half_rn(lo_elem))
         | ((uint32_t)__half_as_ushort(__float2half_rn(hi_elem)) << 16);
}
// fast sigmoid/tanh via MUFU (err ~2^-21)
__device__ __forceinline__ float fsig(float x){
    float e; asm("ex2.approx.ftz.f32 %0, %1;" : "=f"(e) : "f"(-1.4426950408889634f * x));
    float r; asm("rcp.approx.ftz.f32 %0, %1;" : "=f"(r) : "f"(1.f + e));
    return r;
}
__device__ __forceinline__ float ftanh(float x){ return 2.f * fsig(2.f * x) - 1.f; }

// ---------------- prep ----------------
__global__ void k_prep(const float* __restrict__ Whh, const float* __restrict__ fcw){
    int i = blockIdx.x * blockDim.x + threadIdx.x;
    if (i < HFRAG_E) g_hfrag[(size_t)512 * HFRAG_E + i] = __float2half(0.f);
    if (i < NCTA * 32) g_flag[i] = 0u;
    if (i < FCF_U2){
        int vt = i / 1536, r = i % 1536, kc = r / 32, lane = r & 31;
        int col = vt * 8 + (lane >> 2);
        const float* wr = fcw + (size_t)col * HH + kc * 16 + 2 * (lane & 3);
        uint2 v;
        v.x = pack_h2(wr[0], wr[1]);
        v.y = pack_h2(wr[8], wr[9]);
        g_fcfrag[i] = v;
    }
    if (i < NCTA * WFRAG_U4_PER_CTA){
        int cta = i / WFRAG_U4_PER_CTA;
        int j   = i % WFRAG_U4_PER_CTA;
        int kc  = j / 96, j2 = j % 96, nt = j2 >> 5, lane = j2 & 31;
        int lr = lane >> 2, lc = lane & 3;
        int n_local = nt * 8 + lr;
        int u = n_local >> 2, gate = n_local & 3;
        int grow = gate * HH + cta * UPC + u;
        const float* wr = Whh + (size_t)grow * HH + kc * 16;
        float w00 = wr[2*lc],     w01 = wr[2*lc + 1];
        float w10 = wr[2*lc + 8], w11 = wr[2*lc + 9];
        float h00 = __half2float(__float2half_rn(w00));
        float h01 = __half2float(__float2half_rn(w01));
        float h10 = __half2float(__float2half_rn(w10));
        float h11 = __half2float(__float2half_rn(w11));
        uint4 v;
        v.x = pack_h2(h00, h01);
        v.y = pack_h2(h10, h11);
        v.z = pack_h2(w00 - h00, w01 - h01);
        v.w = pack_h2(w10 - h10, w11 - h11);
        g_wfrag[i] = v;
    }
}

// ---------------- tf32 GEMM (proj): C = A[M,K] @ B[N,K]^T + bias1 + bias2 ----------------
__global__ __launch_bounds__(256) void k_gemm(
    const float* __restrict__ A, const float* __restrict__ Bm, float* __restrict__ C,
    int M, int N, int K, const float* __restrict__ bias1, const float* __restrict__ bias2)
{
    __shared__ float As[128][36];
    __shared__ float Bs[128][36];
    const int tid = threadIdx.x;
    const int w = tid >> 5, lane = tid & 31;
    const int lr = lane >> 2, lc = lane & 3;
    const int m0 = blockIdx.y * 128, n0 = blockIdx.x * 128;
    const int wm = (w >> 1) * 32, wn = (w & 1) * 64;
    float acc[2][8][4];
    #pragma unroll
    for (int i = 0; i < 2; i++)
        #pragma unroll
        for (int j = 0; j < 8; j++)
            #pragma unroll
            for (int q = 0; q < 4; q++) acc[i][j][q] = 0.f;
    float4 pa[4], pb[4];
    #pragma unroll
    for (int i = 0; i < 4; i++){
        int f = tid + i * 256; int r = f >> 3, cf = (f & 7) * 4;
        pa[i] = make_float4(0.f,0.f,0.f,0.f);
        if (m0 + r < M) pa[i] = *(const float4*)(A + (size_t)(m0 + r) * K + cf);
        pb[i] = make_float4(0.f,0.f,0.f,0.f);
        if (n0 + r < N) pb[i] = *(const float4*)(Bm + (size_t)(n0 + r) * K + cf);
    }
    for (int k0 = 0; k0 < K; k0 += 32){
        #pragma unroll
        for (int i = 0; i < 4; i++){
            int f = tid + i * 256; int r = f >> 3, cf = (f & 7) * 4;
            float4 ta = pa[i], tb = pb[i];
            As[r][cf+0] = to_tf32(ta.x); As[r][cf+1] = to_tf32(ta.y);
            As[r][cf+2] = to_tf32(ta.z); As[r][cf+3] = to_tf32(ta.w);
            Bs[r][cf+0] = to_tf32(tb.x); Bs[r][cf+1] = to_tf32(tb.y);
            Bs[r][cf+2] = to_tf32(tb.z); Bs[r][cf+3] = to_tf32(tb.w);
        }
        __syncthreads();
        int k1 = k0 + 32;
        if (k1 < K){
            #pragma unroll
            for (int i = 0; i < 4; i++){
                int f = tid + i * 256; int r = f >> 3, cf = (f & 7) * 4;
                pa[i] = make_float4(0.f,0.f,0.f,0.f);
                if (m0 + r < M) pa[i] = *(const float4*)(A + (size_t)(m0 + r) * K + k1 + cf);
                pb[i] = make_float4(0.f,0.f,0.f,0.f);
                if (n0 + r < N) pb[i] = *(const float4*)(Bm + (size_t)(n0 + r) * K + k1 + cf);
            }
        }
        #pragma unroll
        for (int kk = 0; kk < 32; kk += 8){
            uint32_t af[2][4], bf[8][2];
            #pragma unroll
            for (int mt = 0; mt < 2; mt++){
                int rb = wm + mt * 16;
                af[mt][0] = fu(As[rb + lr][kk + lc]);
                af[mt][1] = fu(As[rb + 8 + lr][kk + lc]);
                af[mt][2] = fu(As[rb + lr][kk + lc + 4]);
                af[mt][3] = fu(As[rb + 8 + lr][kk + lc + 4]);
            }
            #pragma unroll
            for (int nt = 0; nt < 8; nt++){
                int cb = wn + nt * 8;
                bf[nt][0] = fu(Bs[cb + lr][kk + lc]);
                bf[nt][1] = fu(Bs[cb + lr][kk + lc + 4]);
            }
            #pragma unroll
            for (int mt = 0; mt < 2; mt++)
                #pragma unroll
                for (int nt = 0; nt < 8; nt++)
                    mma_tf32(acc[mt][nt], af[mt], bf[nt]);
        }
        __syncthreads();
    }
    #pragma unroll
    for (int mt = 0; mt < 2; mt++)
        #pragma unroll
        for (int nt = 0; nt < 8; nt++){
            #pragma unroll
            for (int q = 0; q < 4; q++){
                int row = m0 + wm + mt * 16 + lr + (q >> 1) * 8;
                int col = n0 + wn + nt * 8 + lc * 2 + (q & 1);
                if (row < M && col < N){
                    float v = acc[mt][nt][q];
                    if (bias1) v += bias1[col];
                    if (bias2) v += bias2[col];
                    C[(size_t)row * N + col] = v;
                }
            }
        }
}

// ---------------- persistent: recurrence (warps 0-3) + shadow FC (warps 4-7) ----------------
// 128 CTAs x 256 thr. Gate warps compute gates(t) from h(t-1) [288 mma]; after the barrier
// arrive, FC warps compute out[:, t-1] from the SAME slot t-1 while gate warp 0 polls flags.
__global__ __launch_bounds__(256, 1) void k_persist(const int* __restrict__ x,
                                                    float* __restrict__ out,
                                                    const float* __restrict__ fcb)
{
    extern __shared__ char smraw[];
    uint4* Bsm = (uint4*)smraw;                         // 73728 B
    uint2* Fsm = (uint2*)(smraw + WFRAG_U4_PER_CTA*16); // 61440 B
    float* gs  = (float*)(smraw + WFRAG_U4_PER_CTA*16 + 61440); // 6400 B
    const int tid  = threadIdx.x;
    const int w    = tid >> 5, lane = tid & 31;
    const int lr   = lane >> 2, lc2 = (lane & 3) * 2;
    const int cta  = blockIdx.x;
    const bool has_fc = (cta < 125);
    const bool isgate = (w < 4);
    const int wf = w & 3;            // m16 tile index within group

    {   // persistent weights -> smem
        const uint4* wsrc = g_wfrag + (size_t)cta * WFRAG_U4_PER_CTA;
        for (int i = tid; i < WFRAG_U4_PER_CTA; i += 256) Bsm[i] = wsrc[i];
        if (has_fc){
            const uint2* fsrc = g_fcfrag + (size_t)cta * 5 * NKC * 32;
            for (int i = tid; i < 5 * NKC * 32; i += 256) Fsm[i] = fsrc[i];
        }
    }

    // FC bias regs (FC warps only need them)
    float bv[5][2];
    #pragma unroll
    for (int v = 0; v < 5; v++){
        int col = (cta * 5 + v) * 8 + lc2;
        bv[v][0] = has_fc ? fcb[col] : 0.f;
        bv[v][1] = has_fc ? fcb[col + 1] : 0.f;
    }

    // epilogue items: item0 = tid (all), item1 = tid+256 (tid<128); 384 = 64b x 6u
    int eb[2], eu[2]; float creg[2]; const int* xp[2];
    const bool ev1 = (tid < 128);
    #pragma unroll
    for (int j = 0; j < 2; j++){
        int idx = tid + j * 256;
        eb[j] = idx & 63; eu[j] = (idx >> 6) % UPC;
        creg[j] = 0.f;
        xp[j] = x + eb[j] * TT;
    }
    // pv for t=0
    float pv[2][4];
    #pragma unroll
    for (int j = 0; j < 2; j++){
        if (j == 0 || ev1){
            int xv = __ldg(xp[j]);
            const float* pr = g_proj + (size_t)xv * G4 + (cta * UPC + eu[j]);
            #pragma unroll
            for (int g = 0; g < 4; g++) pv[j][g] = __ldg(pr + g * HH);
        }
    }
    unsigned genreg = 0;
    __syncthreads();

    for (int t = 0; t < TT; t++){
        const uint4* Ah = (const uint4*)(g_hfrag + (size_t)((t == 0) ? 512 : (t - 1)) * HFRAG_E);

        uint4 fring[8];          // FC warps preload their A-ring during the gate phase
        if (isgate){
            float accH[3][4], accL[3][4];
            #pragma unroll
            for (int n = 0; n < 3; n++)
                #pragma unroll
                for (int q = 0; q < 4; q++){ accH[n][q] = 0.f; accL[n][q] = 0.f; }
            uint4 ahb[8];
            #pragma unroll
            for (int j = 0; j < 8; j++)
                ahb[j] = __ldg(Ah + (j * 4 + wf) * 32 + lane);
            for (int c = 0; c < 6; c++){
                #pragma unroll
                for (int j = 0; j < 8; j++){
                    int kc = c * 8 + j;
                    uint4 a4 = ahb[j];
                    if (kc + 8 < NKC)
                        ahb[j] = __ldg(Ah + ((kc + 8) * 4 + wf) * 32 + lane);
                    uint32_t ah[4] = {a4.x, a4.y, a4.z, a4.w};
                    #pragma unroll
                    for (int nt = 0; nt < 3; nt++){
                        uint4 bb = Bsm[(kc * 3 + nt) * 32 + lane];
                        mma_fp16(accH[nt], ah, bb.x, bb.y);
                        mma_fp16(accL[nt], ah, bb.z, bb.w);
                    }
                }
            }
            // gate tile -> smem
            #pragma unroll
            for (int nt = 0; nt < 3; nt++){
                #pragma unroll
                for (int q = 0; q < 4; q++){
                    int row = wf * 16 + lr + (q >> 1) * 8;
                    int col = nt * 8 + lc2 + (q & 1);
                    gs[row * 25 + col] = accH[nt][q] + accL[nt][q];
                }
            }
        } else if (has_fc && t > 0){
            #pragma unroll
            for (int j = 0; j < 8; j++)
                fring[j] = __ldg(Ah + (j * 4 + wf) * 32 + lane);
        }
        __syncthreads();

        // pointwise LSTM + h A-fragment scatter into slot t (all 256 threads)
        __half* hdst = g_hfrag + (size_t)t * HFRAG_E;
        #pragma unroll
        for (int j = 0; j < 2; j++){
            if (j == 1 && !ev1) break;
            int b = eb[j], u = eu[j], ug = cta * UPC + u;
            float gi = gs[b * 25 + 4*u + 0] + pv[j][0];
            float gf = gs[b * 25 + 4*u + 1] + pv[j][1];
            float gg = gs[b * 25 + 4*u + 2] + pv[j][2];
            float go = gs[b * 25 + 4*u + 3] + pv[j][3];
            float cnew = fsig(gf) * creg[j] + fsig(gi) * ftanh(gg);
            float hnew = fsig(go) * ftanh(cnew);
            creg[j] = cnew;
            int kc = ug >> 4, kk = ug & 15;
            int r = b & 15, wb = b >> 4;
            int lane_h = (r & 7) * 4 + ((kk & 7) >> 1);
            int reg = (r >> 3) + 2 * (kk >> 3);
            int half = kk & 1;
            int elem = (((kc * 4 + wb) * 32 + lane_h) * 4 + reg) * 2 + half;
            hdst[elem] = __float2half_rn(hnew);
        }

        __threadfence();
        __syncthreads();
        genreg += 1;
        if (tid == 0)
            asm volatile("st.release.gpu.global.u32 [%0], %1;"
                :: "l"(&g_flag[cta * 32]), "r"(genreg) : "memory");

        // pv prefetch for t+1 (hidden in barrier window)
        if (t + 1 < TT){
            #pragma unroll
            for (int j = 0; j < 2; j++){
                if (j == 1 && !ev1) break;
                int xv = __ldg(xp[j] + t + 1);
                const float* pr = g_proj + (size_t)xv * G4 + (cta * UPC + eu[j]);
                #pragma unroll
                for (int g = 0; g < 4; g++) pv[j][g] = __ldg(pr + g * HH);
            }
        }

        // ---- FC for t-1 in the barrier shadow (warps 4-7) ----
        if (!isgate && has_fc && t > 0){
            float accF[5][4];
            #pragma unroll
            for (int n = 0; n < 5; n++)
                #pragma unroll
                for (int q = 0; q < 4; q++) accF[n][q] = 0.f;
            for (int c = 0; c < 6; c++){
                #pragma unroll
                for (int j = 0; j < 8; j++){
                    int kc = c * 8 + j;
                    uint4 a4 = fring[j];
                    if (kc + 8 < NKC)
                        fring[j] = __ldg(Ah + ((kc + 8) * 4 + wf) * 32 + lane);
                    uint32_t ah[4] = {a4.x, a4.y, a4.z, a4.w};
                    #pragma unroll
                    for (int v = 0; v < 5; v++){
                        uint2 f2 = Fsm[(v * NKC + kc) * 32 + lane];
                        mma_fp16(accF[v], ah, f2.x, f2.y);
                    }
                }
            }
            int tfc = t - 1;
            #pragma unroll
            for (int v = 0; v < 5; v++){
                int colb = (cta * 5 + v) * 8 + lc2;
                #pragma unroll
                for (int h = 0; h < 2; h++){
                    int b = wf * 16 + lr + h * 8;
                    float2 o = make_float2(accF[v][2*h] + bv[v][0], accF[v][2*h+1] + bv[v][1]);
                    *(float2*)(out + (size_t)(b * TT + tfc) * VV + colb) = o;
                }
            }
        }

        if (w == 0){   // gate warp 0 polls all 128 flags
            unsigned f0, f1, f2, f3; unsigned ok;
            do {
                asm volatile("ld.acquire.gpu.global.u32 %0, [%1];" : "=r"(f0) : "l"(&g_flag[lane * 32]));
                asm volatile("ld.acquire.gpu.global.u32 %0, [%1];" : "=r"(f1) : "l"(&g_flag[(lane + 32) * 32]));
                asm volatile("ld.acquire.gpu.global.u32 %0, [%1];" : "=r"(f2) : "l"(&g_flag[(lane + 64) * 32]));
                asm volatile("ld.acquire.gpu.global.u32 %0, [%1];" : "=r"(f3) : "l"(&g_flag[(lane + 96) * 32]));
                ok = ((int)(f0 - genreg) >= 0) && ((int)(f1 - genreg) >= 0)
                  && ((int)(f2 - genreg) >= 0) && ((int)(f3 - genreg) >= 0);
            } while (__ballot_sync(0xffffffffu, ok) != 0xffffffffu);
        }
        __syncthreads();
    }

    // tail: FC for t = 511 (h(511) published by the final barrier)
    if (!isgate && has_fc){
        const uint4* Ah = (const uint4*)(g_hfrag + (size_t)511 * HFRAG_E);
        float accF[5][4];
        #pragma unroll
        for (int n = 0; n < 5; n++)
            #pragma unroll
            for (int q = 0; q < 4; q++) accF[n][q] = 0.f;
        for (int kc = 0; kc < NKC; kc++){
            uint4 a4 = __ldg(Ah + (kc * 4 + wf) * 32 + lane);
            uint32_t ah[4] = {a4.x, a4.y, a4.z, a4.w};
            #pragma unroll
            for (int v = 0; v < 5; v++){
                uint2 f2 = Fsm[(v * NKC + kc) * 32 + lane];
                mma_fp16(accF[v], ah, f2.x, f2.y);
            }
        }
        #pragma unroll
        for (int v = 0; v < 5; v++){
            int colb = (cta * 5 + v) * 8 + lc2;
            #pragma unroll
            for (int h = 0; h < 2; h++){
                int b = wf * 16 + lr + h * 8;
                float2 o = make_float2(accF[v][2*h] + bv[v][0], accF[v][2*h+1] + bv[v][1]);
                *(float2*)(out + (size_t)(b * TT + 511) * VV + colb) = o;
            }
        }
    }
}

// ---------------- host launch ----------------
extern "C" void kernel_launch(void* const* d_in, const int* in_sizes, int n_in,
                              void* d_out, int out_size)
{
    const int* x = 0;
    const float *embed = 0, *W_ih = 0, *W_hh = 0, *b_ih = 0, *b_hh = 0, *fc_w = 0, *fc_b = 0;
    for (int i = 0; i < n_in; i++){
        switch (in_sizes[i]){
            case BB*TT:      x     = (const int*)  d_in[i]; break;
            case VV*EE:      embed = (const float*)d_in[i]; break;
            case G4*EE:      W_ih  = (const float*)d_in[i]; break;
            case G4*HH:      W_hh  = (const float*)d_in[i]; break;
            case G4:         if (!b_ih) b_ih = (const float*)d_in[i];
                             else        b_hh = (const float*)d_in[i]; break;
            case VV*HH:      fc_w  = (const float*)d_in[i]; break;
            case VV:         fc_b  = (const float*)d_in[i]; break;
            default: break;  // truncate_length — identity in forward pass
        }
    }
    float* out = (float*)d_out;
    float* p_proj = 0;
    cudaGetSymbolAddress((void**)&p_proj, g_proj);

    const int SMEM = WFRAG_U4_PER_CTA * 16 + 61440 + 64 * 25 * 4;  // 141568
    cudaFuncSetAttribute(k_persist, cudaFuncAttributeMaxDynamicSharedMemorySize, SMEM);

    // 1) prep: W_hh + fc_w fragments, zero h slot 512 + flags (replay-safe)
    {
        int n = FCF_U2;   // 960000 covers all prep ranges
        k_prep<<<(n + 255) / 256, 256>>>(W_hh, fc_w);
    }
    // 2) proj[V,4H] = embed @ W_ih^T + b_ih + b_hh  (tf32)
    {
        dim3 grid(G4 / 128, (VV + 127) / 128);
        k_gemm<<<grid, 256>>>(embed, W_ih, p_proj, VV, G4, EE, b_ih, b_hh);
    }
    // 3) persistent recurrence + shadow FC: 1 launch
    k_persist<<<NCTA, 256, SMEM>>>(x, out, fc_b);
}